// round 1
// baseline (speedup 1.0000x reference)
#include <cuda_runtime.h>
#include <cstdint>

// Problem constants
#define BT   65536
#define Dk   256
#define Hk   512
#define Ck   10
#define Pk   10
#define HPk  128

// Tiling
#define ROWS     64          // rows per block
#define NTHREADS 256
#define HCHUNK   128         // H processed per chunk (4 chunks)
#define NHC      (Hk / HCHUNK)
#define KSLAB    16          // K slab for Wt1 staging
#define XSS      257         // padded x row stride in smem (floats)

// Shared-memory layout (floats first, then ints)
#define XS_F    (ROWS * XSS)          // 16448 floats
#define WS_F    (KSLAB * HCHUNK)      // 2048 floats
#define OUTS_F  (ROWS * Ck)           // 640 floats
#define SMEM_FLOATS (XS_F + WS_F + OUTS_F)
#define SMEM_INTS   (Pk * ROWS + Pk + (Pk + 1))   // lists, cnt, poff
#define SMEM_BYTES  ((SMEM_FLOATS + SMEM_INTS) * 4)

__global__ void __launch_bounds__(NTHREADS)
netsum_kernel(const float* __restrict__ x,
              const float* __restrict__ Wt1, const float* __restrict__ bt1,
              const float* __restrict__ Wt2, const float* __restrict__ bt2,
              const float* __restrict__ Wp1, const float* __restrict__ bp1,
              const float* __restrict__ Wp2, const float* __restrict__ bp2,
              const int*   __restrict__ rdd,
              float* __restrict__ out)
{
    extern __shared__ float smem[];
    float* xs    = smem;                       // [ROWS][XSS]
    float* ws    = xs + XS_F;                  // [KSLAB][HCHUNK]
    float* outs  = ws + WS_F;                  // [ROWS][Ck]
    int*   lists = (int*)(outs + OUTS_F);      // [Pk][ROWS]
    int*   cnt   = lists + Pk * ROWS;          // [Pk]
    int*   poff  = cnt + Pk;                   // [Pk+1]

    const int tid  = threadIdx.x;
    const int row0 = blockIdx.x * ROWS;

    // ---- Load x tile into smem: thread -> (row = tid/4, 64-float segment = tid%4)
    {
        const int r   = tid >> 2;
        const int seg = tid & 3;
        const float4* src = (const float4*)(x + (size_t)(row0 + r) * Dk + seg * 64);
        float* dst = xs + r * XSS + seg * 64;
        #pragma unroll
        for (int i = 0; i < 16; i++) {
            float4 v = src[i];
            dst[i * 4 + 0] = v.x; dst[i * 4 + 1] = v.y;
            dst[i * 4 + 2] = v.z; dst[i * 4 + 3] = v.w;
        }
    }
    if (tid < Pk) cnt[tid] = 0;
    __syncthreads();

    // ---- GEMM1 (x @ Wt1 + bt1, ReLU) fused with GEMM2 (h1 @ Wt2) partials
    const int ty = tid >> 4;   // 0..15 -> 4 rows each
    const int tx = tid & 15;   // 0..15 -> 8 H-cols each (per chunk)

    float pout[4][Ck];
    #pragma unroll
    for (int i = 0; i < 4; i++)
        #pragma unroll
        for (int c = 0; c < Ck; c++) pout[i][c] = 0.f;

    for (int hc = 0; hc < NHC; hc++) {
        float acc[4][8];
        #pragma unroll
        for (int j = 0; j < 8; j++) {
            float bv = __ldg(bt1 + hc * HCHUNK + tx * 8 + j);
            #pragma unroll
            for (int i = 0; i < 4; i++) acc[i][j] = bv;
        }

        for (int k0 = 0; k0 < Dk; k0 += KSLAB) {
            __syncthreads();
            {   // stage Wt1[k0..k0+15][hc*128 .. +128) -> ws
                const int kk   = tid >> 4;
                const int hseg = tid & 15;
                const float4* src = (const float4*)(Wt1 + (size_t)(k0 + kk) * Hk
                                                    + hc * HCHUNK + hseg * 8);
                float4 v0 = __ldg(src + 0);
                float4 v1 = __ldg(src + 1);
                float4* dst = (float4*)(ws + kk * HCHUNK + hseg * 8);
                dst[0] = v0; dst[1] = v1;
            }
            __syncthreads();

            #pragma unroll
            for (int kk = 0; kk < KSLAB; kk++) {
                float a[4];
                #pragma unroll
                for (int i = 0; i < 4; i++)
                    a[i] = xs[(ty * 4 + i) * XSS + (k0 + kk)];
                const float4* bp = (const float4*)(ws + kk * HCHUNK + tx * 8);
                float4 b0 = bp[0], b1 = bp[1];
                float b[8] = {b0.x, b0.y, b0.z, b0.w, b1.x, b1.y, b1.z, b1.w};
                #pragma unroll
                for (int i = 0; i < 4; i++)
                    #pragma unroll
                    for (int j = 0; j < 8; j++)
                        acc[i][j] += a[i] * b[j];
            }
        }

        // ReLU + GEMM2 partial into registers
        #pragma unroll
        for (int j = 0; j < 8; j++) {
            const int hg = hc * HCHUNK + tx * 8 + j;
            const float* w2 = Wt2 + (size_t)hg * Ck;
            float wv[Ck];
            #pragma unroll
            for (int c = 0; c < Ck; c++) wv[c] = __ldg(w2 + c);
            #pragma unroll
            for (int i = 0; i < 4; i++) {
                float hv = fmaxf(acc[i][j], 0.f);
                #pragma unroll
                for (int c = 0; c < Ck; c++) pout[i][c] += hv * wv[c];
            }
        }
    }

    // ---- Reduce pout across the 16 tx lanes (two independent 16-lane halves per warp)
    #pragma unroll
    for (int i = 0; i < 4; i++)
        #pragma unroll
        for (int c = 0; c < Ck; c++) {
            float v = pout[i][c];
            v += __shfl_xor_sync(0xffffffffu, v, 8);
            v += __shfl_xor_sync(0xffffffffu, v, 4);
            v += __shfl_xor_sync(0xffffffffu, v, 2);
            v += __shfl_xor_sync(0xffffffffu, v, 1);
            pout[i][c] = v;
        }
    if (tx == 0) {
        #pragma unroll
        for (int i = 0; i < 4; i++)
            #pragma unroll
            for (int c = 0; c < Ck; c++)
                outs[(ty * 4 + i) * Ck + c] = pout[i][c] + __ldg(bt2 + c);
    }
    __syncthreads();

    // ---- Top-2 (JAX tie semantics: lowest index wins), bitmap, per-p worklists
    if (tid < ROWS) {
        float v[Ck];
        #pragma unroll
        for (int c = 0; c < Ck; c++) v[c] = outs[tid * Ck + c];
        int i1 = 0; float m1 = v[0];
        #pragma unroll
        for (int c = 1; c < Ck; c++) if (v[c] > m1) { m1 = v[c]; i1 = c; }
        int i2 = -1; float m2 = -3.0e38f;
        #pragma unroll
        for (int c = 0; c < Ck; c++)
            if (c != i1 && v[c] > m2) { m2 = v[c]; i2 = c; }

        unsigned mask_in = 0u, mask_fb = 0u;
        #pragma unroll
        for (int p = 0; p < Pk; p++) {
            int a = __ldg(rdd + 2 * p), b = __ldg(rdd + 2 * p + 1);
            if (i1 == a && i2 == b) mask_in |= (1u << p);
            if (i1 == a)            mask_fb |= (1u << p);
        }
        unsigned m = mask_in ? mask_in : mask_fb;
        while (m) {
            int p = __ffs(m) - 1; m &= m - 1;
            int slot = atomicAdd(&cnt[p], 1);
            lists[p * ROWS + slot] = tid;
        }
    }
    __syncthreads();
    if (tid == 0) {
        int s = 0;
        #pragma unroll
        for (int p = 0; p < Pk; p++) { poff[p] = s; s += cnt[p]; }
        poff[Pk] = s;
    }
    __syncthreads();

    // ---- Patch phase: one warp per active (p, row) pair
    const int total = poff[Pk];
    const int warp = tid >> 5, lane = tid & 31;
    for (int g = warp; g < total; g += (NTHREADS / 32)) {
        int p = 0;
        #pragma unroll
        for (int q = 0; q < Pk - 1; q++) if (g >= poff[q + 1]) p = q + 1;
        const int row = lists[p * ROWS + (g - poff[p])];

        const float* xrow = xs + row * XSS;
        const float4* wbase = (const float4*)Wp1 + (size_t)p * Dk * (HPk / 4) + lane;
        float4 hp = make_float4(0.f, 0.f, 0.f, 0.f);
        #pragma unroll 4
        for (int d = 0; d < Dk; d++) {
            float xv = xrow[d];
            float4 w = __ldg(wbase + (size_t)d * (HPk / 4));
            hp.x += xv * w.x; hp.y += xv * w.y;
            hp.z += xv * w.z; hp.w += xv * w.w;
        }
        const float* b1 = bp1 + p * HPk + lane * 4;
        hp.x = fmaxf(hp.x + __ldg(b1 + 0), 0.f);
        hp.y = fmaxf(hp.y + __ldg(b1 + 1), 0.f);
        hp.z = fmaxf(hp.z + __ldg(b1 + 2), 0.f);
        hp.w = fmaxf(hp.w + __ldg(b1 + 3), 0.f);

        float po[Ck];
        #pragma unroll
        for (int c = 0; c < Ck; c++) po[c] = 0.f;
        const float* w2 = Wp2 + ((size_t)p * HPk + lane * 4) * Ck;
        const float hv4[4] = {hp.x, hp.y, hp.z, hp.w};
        #pragma unroll
        for (int j = 0; j < 4; j++) {
            float hv = hv4[j];
            #pragma unroll
            for (int c = 0; c < Ck; c++) po[c] += hv * __ldg(w2 + j * Ck + c);
        }
        #pragma unroll
        for (int c = 0; c < Ck; c++) {
            float v = po[c];
            v += __shfl_xor_sync(0xffffffffu, v, 16);
            v += __shfl_xor_sync(0xffffffffu, v, 8);
            v += __shfl_xor_sync(0xffffffffu, v, 4);
            v += __shfl_xor_sync(0xffffffffu, v, 2);
            v += __shfl_xor_sync(0xffffffffu, v, 1);
            po[c] = v;
        }
        if (lane == 0) {
            #pragma unroll
            for (int c = 0; c < Ck; c++)
                atomicAdd(&outs[row * Ck + c], po[c] + __ldg(bp2 + p * Ck + c));
        }
    }
    __syncthreads();

    // ---- Write final out tile
    for (int idx = tid; idx < ROWS * Ck; idx += NTHREADS)
        out[(size_t)row0 * Ck + idx] = outs[idx];
}

extern "C" void kernel_launch(void* const* d_in, const int* in_sizes, int n_in,
                              void* d_out, int out_size)
{
    const float* x   = (const float*)d_in[0];
    const float* Wt1 = (const float*)d_in[1];
    const float* bt1 = (const float*)d_in[2];
    const float* Wt2 = (const float*)d_in[3];
    const float* bt2 = (const float*)d_in[4];
    const float* Wp1 = (const float*)d_in[5];
    const float* bp1 = (const float*)d_in[6];
    const float* Wp2 = (const float*)d_in[7];
    const float* bp2 = (const float*)d_in[8];
    const int*   rdd = (const int*)d_in[9];
    float* out = (float*)d_out;

    cudaFuncSetAttribute(netsum_kernel,
                         cudaFuncAttributeMaxDynamicSharedMemorySize, SMEM_BYTES);

    dim3 grid(BT / ROWS);
    netsum_kernel<<<grid, NTHREADS, SMEM_BYTES>>>(
        x, Wt1, bt1, Wt2, bt2, Wp1, bp1, Wp2, bp2, rdd, out);
}

// round 3
// speedup vs baseline: 1.1287x; 1.1287x over previous
#include <cuda_runtime.h>
#include <cstdint>

// Problem constants
#define BT   65536
#define Dk   256
#define Hk   512
#define Ck   10
#define Pk   10
#define HPk  128

// Tiling
#define ROWS     64
#define NTHREADS 256
#define HCHUNK   128
#define NHC      (Hk / HCHUNK)
#define KSLAB    32
#define XTS      68            // padded stride of transposed x tile (floats)

// Shared memory layout
#define XT_F    (Dk * XTS)            // 17408 floats (transposed x: [D][XTS])
#define WS_F    (KSLAB * HCHUNK)      // 4096 floats
#define OUTS_F  (ROWS * Ck)           // 640 floats
#define SMEM_FLOATS (XT_F + WS_F + OUTS_F)
#define SMEM_INTS   (Pk * ROWS + Pk + (Pk + 1))
#define SMEM_BYTES  ((SMEM_FLOATS + SMEM_INTS) * 4)

__global__ void __launch_bounds__(NTHREADS)
netsum_kernel(const float* __restrict__ x,
              const float* __restrict__ Wt1, const float* __restrict__ bt1,
              const float* __restrict__ Wt2, const float* __restrict__ bt2,
              const float* __restrict__ Wp1, const float* __restrict__ bp1,
              const float* __restrict__ Wp2, const float* __restrict__ bp2,
              const int*   __restrict__ rdd,
              float* __restrict__ out)
{
    extern __shared__ float smem[];
    float* xt    = smem;                       // [Dk][XTS] transposed x tile
    float* ws    = xt + XT_F;                  // [KSLAB][HCHUNK]
    float* outs  = ws + WS_F;                  // [ROWS][Ck]
    int*   lists = (int*)(outs + OUTS_F);      // [Pk][ROWS]
    int*   cnt   = lists + Pk * ROWS;          // [Pk]
    int*   goff  = cnt + Pk;                   // [Pk+1] group offsets

    const int tid  = threadIdx.x;
    const int row0 = blockIdx.x * ROWS;

    // ---- Load x tile, transposed into smem.
    // seg = tid>>6 selects 64 consecutive d's; r = tid&63 is the row.
    // STS pattern: lanes have consecutive r for a fixed d -> conflict-free.
    {
        const int seg = tid >> 6;
        const int r   = tid & 63;
        const float4* src = (const float4*)(x + (size_t)(row0 + r) * Dk + seg * 64);
        #pragma unroll
        for (int i = 0; i < 16; i++) {
            float4 v = src[i];
            const int d = seg * 64 + i * 4;
            xt[(d + 0) * XTS + r] = v.x;
            xt[(d + 1) * XTS + r] = v.y;
            xt[(d + 2) * XTS + r] = v.z;
            xt[(d + 3) * XTS + r] = v.w;
        }
    }
    if (tid < Pk) cnt[tid] = 0;
    __syncthreads();

    // ---- GEMM1 (x @ Wt1 + bt1, ReLU) fused with GEMM2 (h1 @ Wt2) partials
    const int ty = tid >> 4;   // 0..15 -> 4 rows each
    const int tx = tid & 15;   // 0..15 -> 8 H-cols each (per chunk)

    float pout[4][Ck];
    #pragma unroll
    for (int i = 0; i < 4; i++)
        #pragma unroll
        for (int c = 0; c < Ck; c++) pout[i][c] = 0.f;

    for (int hc = 0; hc < NHC; hc++) {
        float acc[4][8];
        #pragma unroll
        for (int j = 0; j < 8; j++) {
            float bv = __ldg(bt1 + hc * HCHUNK + tx * 8 + j);
            #pragma unroll
            for (int i = 0; i < 4; i++) acc[i][j] = bv;
        }

        for (int k0 = 0; k0 < Dk; k0 += KSLAB) {
            __syncthreads();
            {   // stage Wt1[k0..k0+31][hc*128 .. +128) -> ws (each thread 16 floats)
                const int kk   = tid >> 3;          // 0..31
                const int hseg = tid & 7;           // 0..7 (16 floats each)
                const float4* src = (const float4*)(Wt1 + (size_t)(k0 + kk) * Hk
                                                    + hc * HCHUNK + hseg * 16);
                float4 v0 = __ldg(src + 0);
                float4 v1 = __ldg(src + 1);
                float4 v2 = __ldg(src + 2);
                float4 v3 = __ldg(src + 3);
                float4* dst = (float4*)(ws + kk * HCHUNK + hseg * 16);
                dst[0] = v0; dst[1] = v1; dst[2] = v2; dst[3] = v3;
            }
            __syncthreads();

            #pragma unroll
            for (int kk = 0; kk < KSLAB; kk++) {
                // one broadcast LDS.128 for the 4 row values
                float4 a4 = *(const float4*)(xt + (k0 + kk) * XTS + ty * 4);
                const float4* bp = (const float4*)(ws + kk * HCHUNK + tx * 8);
                float4 b0 = bp[0], b1 = bp[1];
                float a[4] = {a4.x, a4.y, a4.z, a4.w};
                float b[8] = {b0.x, b0.y, b0.z, b0.w, b1.x, b1.y, b1.z, b1.w};
                #pragma unroll
                for (int i = 0; i < 4; i++)
                    #pragma unroll
                    for (int j = 0; j < 8; j++)
                        acc[i][j] += a[i] * b[j];
            }
        }

        // ReLU + GEMM2 partial into registers (Wt2 rows via float2 loads)
        #pragma unroll
        for (int j = 0; j < 8; j++) {
            const int hg = hc * HCHUNK + tx * 8 + j;
            const float2* w2v = (const float2*)(Wt2 + (size_t)hg * Ck);
            float2 w0 = __ldg(w2v + 0), w1 = __ldg(w2v + 1), w2_ = __ldg(w2v + 2),
                   w3 = __ldg(w2v + 3), w4 = __ldg(w2v + 4);
            float wv[Ck] = {w0.x, w0.y, w1.x, w1.y, w2_.x, w2_.y, w3.x, w3.y, w4.x, w4.y};
            #pragma unroll
            for (int i = 0; i < 4; i++) {
                float hv = fmaxf(acc[i][j], 0.f);
                #pragma unroll
                for (int c = 0; c < Ck; c++) pout[i][c] += hv * wv[c];
            }
        }
    }

    // ---- Reduce pout across the 16 tx lanes
    #pragma unroll
    for (int i = 0; i < 4; i++)
        #pragma unroll
        for (int c = 0; c < Ck; c++) {
            float v = pout[i][c];
            v += __shfl_xor_sync(0xffffffffu, v, 8);
            v += __shfl_xor_sync(0xffffffffu, v, 4);
            v += __shfl_xor_sync(0xffffffffu, v, 2);
            v += __shfl_xor_sync(0xffffffffu, v, 1);
            pout[i][c] = v;
        }
    if (tx == 0) {
        #pragma unroll
        for (int i = 0; i < 4; i++)
            #pragma unroll
            for (int c = 0; c < Ck; c++)
                outs[(ty * 4 + i) * Ck + c] = pout[i][c] + __ldg(bt2 + c);
    }
    __syncthreads();

    // ---- Top-2 (JAX tie semantics), bitmap, per-p worklists
    if (tid < ROWS) {
        float v[Ck];
        #pragma unroll
        for (int c = 0; c < Ck; c++) v[c] = outs[tid * Ck + c];
        int i1 = 0; float m1 = v[0];
        #pragma unroll
        for (int c = 1; c < Ck; c++) if (v[c] > m1) { m1 = v[c]; i1 = c; }
        int i2 = -1; float m2 = -3.0e38f;
        #pragma unroll
        for (int c = 0; c < Ck; c++)
            if (c != i1 && v[c] > m2) { m2 = v[c]; i2 = c; }

        unsigned mask_in = 0u, mask_fb = 0u;
        #pragma unroll
        for (int p = 0; p < Pk; p++) {
            int a = __ldg(rdd + 2 * p), b = __ldg(rdd + 2 * p + 1);
            if (i1 == a && i2 == b) mask_in |= (1u << p);
            if (i1 == a)            mask_fb |= (1u << p);
        }
        unsigned m = mask_in ? mask_in : mask_fb;
        while (m) {
            int p = __ffs(m) - 1; m &= m - 1;
            int slot = atomicAdd(&cnt[p], 1);
            lists[p * ROWS + slot] = tid;
        }
    }
    __syncthreads();
    if (tid == 0) {
        int s = 0;
        #pragma unroll
        for (int p = 0; p < Pk; p++) { goff[p] = s; s += (cnt[p] + 3) >> 2; }
        goff[Pk] = s;
    }
    __syncthreads();

    // ---- Patch phase: one warp per (p, group-of-4-rows) task.
    // Wp1[p] is streamed ONCE per group instead of once per row (4x traffic cut).
    const int ngroups = goff[Pk];
    const int warp = tid >> 5, lane = tid & 31;
    for (int g = warp; g < ngroups; g += (NTHREADS / 32)) {
        int p = 0;
        #pragma unroll
        for (int q = 0; q < Pk - 1; q++) if (g >= goff[q + 1]) p = q + 1;
        const int base = (g - goff[p]) * 4;
        const int nv   = min(4, cnt[p] - base);

        int rows[4];
        rows[0] = lists[p * ROWS + base];
        #pragma unroll
        for (int j = 1; j < 4; j++)
            rows[j] = (j < nv) ? lists[p * ROWS + base + j] : rows[0];

        const float4* wbase = (const float4*)Wp1 + (size_t)p * Dk * (HPk / 4) + lane;
        float4 hp[4];
        #pragma unroll
        for (int j = 0; j < 4; j++) hp[j] = make_float4(0.f, 0.f, 0.f, 0.f);

        #pragma unroll 8
        for (int d = 0; d < Dk; d++) {
            float4 w = __ldg(wbase + (size_t)d * (HPk / 4));
            #pragma unroll
            for (int j = 0; j < 4; j++) {
                float xv = xt[d * XTS + rows[j]];   // broadcast LDS
                hp[j].x += xv * w.x; hp[j].y += xv * w.y;
                hp[j].z += xv * w.z; hp[j].w += xv * w.w;
            }
        }

        const float* b1 = bp1 + p * HPk + lane * 4;
        float bb0 = __ldg(b1 + 0), bb1 = __ldg(b1 + 1),
              bb2 = __ldg(b1 + 2), bb3 = __ldg(b1 + 3);
        const float2* w2v = (const float2*)(Wp2 + (size_t)(p * HPk + lane * 4) * Ck);
        float wv[4][Ck];
        #pragma unroll
        for (int jj = 0; jj < 4; jj++) {
            float2 q0 = __ldg(w2v + jj * 5 + 0), q1 = __ldg(w2v + jj * 5 + 1),
                   q2 = __ldg(w2v + jj * 5 + 2), q3 = __ldg(w2v + jj * 5 + 3),
                   q4 = __ldg(w2v + jj * 5 + 4);
            wv[jj][0]=q0.x; wv[jj][1]=q0.y; wv[jj][2]=q1.x; wv[jj][3]=q1.y;
            wv[jj][4]=q2.x; wv[jj][5]=q2.y; wv[jj][6]=q3.x; wv[jj][7]=q3.y;
            wv[jj][8]=q4.x; wv[jj][9]=q4.y;
        }

        for (int j = 0; j < nv; j++) {
            float h0 = fmaxf(hp[j].x + bb0, 0.f);
            float h1 = fmaxf(hp[j].y + bb1, 0.f);
            float h2 = fmaxf(hp[j].z + bb2, 0.f);
            float h3 = fmaxf(hp[j].w + bb3, 0.f);
            float po[Ck];
            #pragma unroll
            for (int c = 0; c < Ck; c++)
                po[c] = h0 * wv[0][c] + h1 * wv[1][c] + h2 * wv[2][c] + h3 * wv[3][c];
            #pragma unroll
            for (int c = 0; c < Ck; c++) {
                float v = po[c];
                v += __shfl_xor_sync(0xffffffffu, v, 16);
                v += __shfl_xor_sync(0xffffffffu, v, 8);
                v += __shfl_xor_sync(0xffffffffu, v, 4);
                v += __shfl_xor_sync(0xffffffffu, v, 2);
                v += __shfl_xor_sync(0xffffffffu, v, 1);
                po[c] = v;
            }
            if (lane == 0) {
                #pragma unroll
                for (int c = 0; c < Ck; c++)
                    atomicAdd(&outs[rows[j] * Ck + c], po[c] + __ldg(bp2 + p * Ck + c));
            }
        }
    }
    __syncthreads();

    // ---- Write final out tile
    for (int idx = tid; idx < ROWS * Ck; idx += NTHREADS)
        out[(size_t)row0 * Ck + idx] = outs[idx];
}

extern "C" void kernel_launch(void* const* d_in, const int* in_sizes, int n_in,
                              void* d_out, int out_size)
{
    const float* x   = (const float*)d_in[0];
    const float* Wt1 = (const float*)d_in[1];
    const float* bt1 = (const float*)d_in[2];
    const float* Wt2 = (const float*)d_in[3];
    const float* bt2 = (const float*)d_in[4];
    const float* Wp1 = (const float*)d_in[5];
    const float* bp1 = (const float*)d_in[6];
    const float* Wp2 = (const float*)d_in[7];
    const float* bp2 = (const float*)d_in[8];
    const int*   rdd = (const int*)d_in[9];
    float* out = (float*)d_out;

    cudaFuncSetAttribute(netsum_kernel,
                         cudaFuncAttributeMaxDynamicSharedMemorySize, SMEM_BYTES);

    dim3 grid(BT / ROWS);
    netsum_kernel<<<grid, NTHREADS, SMEM_BYTES>>>(
        x, Wt1, bt1, Wt2, bt2, Wp1, bp1, Wp2, bp2, rdd, out);
}

// round 7
// speedup vs baseline: 1.5550x; 1.3778x over previous
#include <cuda_runtime.h>
#include <cstdint>

// ---------------- problem constants ----------------
#define BT   65536
#define Dk   256
#define Hk   512
#define Ck   10
#define Pk   10
#define HPk  128

#define MROWS 128          // rows per CTA
#define NT    512
#define NWARP 16
#define KSLAB 128          // k rows staged per slab (2 slabs per hc)
#define XSS   260          // xs row stride (floats)
#define GSZ   8            // patch rows per warp-group

// ---------------- smem layout (floats, then ints) ----------------
#define XS_F    (MROWS * XSS)        // 33280
#define WS_F    (KSLAB * 128)        // 16384
#define OUTS_F  (MROWS * Ck)         // 1280
#define SMEM_FLOATS (XS_F + WS_F + OUTS_F)
#define SMEM_INTS   (Pk * MROWS + Pk + (Pk + 1))
#define SMEM_BYTES  ((SMEM_FLOATS + SMEM_INTS) * 4)

typedef unsigned long long u64;

// ---------------- f32x2 helpers (FFMA2 path) ----------------
__device__ __forceinline__ u64 pk2(float a, float b) {
    u64 r; asm("mov.b64 %0, {%1, %2};" : "=l"(r) : "f"(a), "f"(b)); return r;
}
__device__ __forceinline__ u64 dup2(float a) { return pk2(a, a); }
__device__ __forceinline__ float2 upk(u64 v) {
    float2 f; asm("mov.b64 {%0, %1}, %2;" : "=f"(f.x), "=f"(f.y) : "l"(v)); return f;
}
__device__ __forceinline__ void fma2(u64& d, u64 a, u64 b) {
    asm("fma.rn.f32x2 %0, %1, %2, %0;" : "+l"(d) : "l"(a), "l"(b));
}
__device__ __forceinline__ u64 add2(u64 a, u64 b) {
    u64 r; asm("add.rn.f32x2 %0, %1, %2;" : "=l"(r) : "l"(a), "l"(b)); return r;
}

__global__ void __launch_bounds__(NT)
netsum_kernel(const float* __restrict__ x,
              const float* __restrict__ Wt1, const float* __restrict__ bt1,
              const float* __restrict__ Wt2, const float* __restrict__ bt2,
              const float* __restrict__ Wp1, const float* __restrict__ bp1,
              const float* __restrict__ Wp2, const float* __restrict__ bp2,
              const int*   __restrict__ rdd,
              float* __restrict__ out)
{
    extern __shared__ float smem[];
    float* xs    = smem;                       // [MROWS][XSS] row-major x tile
    float* ws    = xs + XS_F;                  // [KSLAB][128] Wt1 slab
    float* outs  = ws + WS_F;                  // [MROWS][Ck]
    int*   lists = (int*)(outs + OUTS_F);      // [Pk][MROWS]
    int*   cnt   = lists + Pk * MROWS;         // [Pk]
    int*   goff  = cnt + Pk;                   // [Pk+1]

    const int tid  = threadIdx.x;
    const int wid  = tid >> 5;
    const int lane = tid & 31;
    const int row0 = blockIdx.x * MROWS;

    // ---- x tile copy (row-major): r = tid>>2, seg = tid&3 covers 64 floats
    {
        const int r = tid >> 2, seg = tid & 3;
        const float4* src = (const float4*)(x + (size_t)(row0 + r) * Dk + seg * 64);
        float4* dst = (float4*)(xs + r * XSS + seg * 64);
        #pragma unroll
        for (int i = 0; i < 16; i++) dst[i] = __ldg(src + i);
    }
    if (tid < Pk) cnt[tid] = 0;
    __syncthreads();

    // ---- fused GEMM1 + GEMM2 partials ----
    const int ty = tid >> 4;   // 0..31 -> rows ty*4..+3
    const int tx = tid & 15;   // cols {2tx + 32j} within each 128-wide hc chunk

    u64 pout[4][5];
    #pragma unroll
    for (int i = 0; i < 4; i++)
        #pragma unroll
        for (int pc = 0; pc < 5; pc++) pout[i][pc] = 0ull;

    #pragma unroll 1
    for (int hc = 0; hc < 4; hc++) {
        u64 acc[4][4];
        #pragma unroll
        for (int jp = 0; jp < 4; jp++) {
            float2 bv = __ldg((const float2*)(bt1 + hc * 128) + tx + 16 * jp);
            u64 b2 = pk2(bv.x, bv.y);
            #pragma unroll
            for (int i = 0; i < 4; i++) acc[i][jp] = b2;
        }

        #pragma unroll 1
        for (int k0 = 0; k0 < Dk; k0 += KSLAB) {
            __syncthreads();
            {   // stage Wt1[k0..k0+127][hc*128..+128): thread -> (kk=tid>>2, 32 floats)
                const int kk = tid >> 2, sg = tid & 3;
                const float4* src = (const float4*)(Wt1 + (size_t)(k0 + kk) * Hk
                                                    + hc * 128 + sg * 32);
                float4* dst = (float4*)(ws + kk * 128 + sg * 32);
                #pragma unroll
                for (int i = 0; i < 8; i++) dst[i] = __ldg(src + i);
            }
            __syncthreads();

            #pragma unroll 4
            for (int kk = 0; kk < KSLAB; kk += 2) {
                // a: float2 (k, k+1) per row — broadcast LDS.64
                float2 a01[4];
                #pragma unroll
                for (int i = 0; i < 4; i++)
                    a01[i] = *(const float2*)(xs + (ty * 4 + i) * XSS + k0 + kk);
                // b: natural col pairs for both k's
                u64 b0[4], b1[4];
                #pragma unroll
                for (int jp = 0; jp < 4; jp++) {
                    float2 v0 = *(const float2*)(ws + kk * 128 + 2 * tx + 32 * jp);
                    float2 v1 = *(const float2*)(ws + (kk + 1) * 128 + 2 * tx + 32 * jp);
                    b0[jp] = pk2(v0.x, v0.y);
                    b1[jp] = pk2(v1.x, v1.y);
                }
                #pragma unroll
                for (int i = 0; i < 4; i++) {
                    u64 ax = dup2(a01[i].x), ay = dup2(a01[i].y);
                    #pragma unroll
                    for (int jp = 0; jp < 4; jp++) {
                        fma2(acc[i][jp], ax, b0[jp]);
                        fma2(acc[i][jp], ay, b1[jp]);
                    }
                }
            }
        }

        // GEMM2 partials: relu(acc) @ Wt2 (wv natural pairs, hot in L1)
        #pragma unroll
        for (int jp = 0; jp < 4; jp++) {
            const int hg = hc * 128 + 2 * tx + 32 * jp;
            const float2* w0 = (const float2*)(Wt2 + (size_t)hg * Ck);
            const float2* w1 = (const float2*)(Wt2 + (size_t)(hg + 1) * Ck);
            u64 wv0[5], wv1[5];
            #pragma unroll
            for (int pc = 0; pc < 5; pc++) {
                float2 a = __ldg(w0 + pc), b = __ldg(w1 + pc);
                wv0[pc] = pk2(a.x, a.y);
                wv1[pc] = pk2(b.x, b.y);
            }
            #pragma unroll
            for (int i = 0; i < 4; i++) {
                float2 h = upk(acc[i][jp]);
                u64 h0 = dup2(fmaxf(h.x, 0.f));
                u64 h1 = dup2(fmaxf(h.y, 0.f));
                #pragma unroll
                for (int pc = 0; pc < 5; pc++) {
                    fma2(pout[i][pc], h0, wv0[pc]);
                    fma2(pout[i][pc], h1, wv1[pc]);
                }
            }
        }
    }

    // ---- reduce pout across the 16 tx lanes (two 16-lane halves per warp)
    #pragma unroll
    for (int i = 0; i < 4; i++)
        #pragma unroll
        for (int pc = 0; pc < 5; pc++) {
            u64 v = pout[i][pc];
            v = add2(v, __shfl_xor_sync(0xffffffffu, v, 8));
            v = add2(v, __shfl_xor_sync(0xffffffffu, v, 4));
            v = add2(v, __shfl_xor_sync(0xffffffffu, v, 2));
            v = add2(v, __shfl_xor_sync(0xffffffffu, v, 1));
            pout[i][pc] = v;
        }
    if (tx == 0) {
        #pragma unroll
        for (int i = 0; i < 4; i++)
            #pragma unroll
            for (int pc = 0; pc < 5; pc++) {
                float2 v = upk(pout[i][pc]);
                outs[(ty * 4 + i) * Ck + 2 * pc]     = v.x + __ldg(bt2 + 2 * pc);
                outs[(ty * 4 + i) * Ck + 2 * pc + 1] = v.y + __ldg(bt2 + 2 * pc + 1);
            }
    }
    __syncthreads();

    // ---- top-2 (JAX tie semantics), bitmap, per-p worklists
    if (tid < MROWS) {
        float v[Ck];
        #pragma unroll
        for (int c = 0; c < Ck; c++) v[c] = outs[tid * Ck + c];
        int i1 = 0; float m1 = v[0];
        #pragma unroll
        for (int c = 1; c < Ck; c++) if (v[c] > m1) { m1 = v[c]; i1 = c; }
        int i2 = -1; float m2 = -3.0e38f;
        #pragma unroll
        for (int c = 0; c < Ck; c++)
            if (c != i1 && v[c] > m2) { m2 = v[c]; i2 = c; }

        unsigned mask_in = 0u, mask_fb = 0u;
        #pragma unroll
        for (int p = 0; p < Pk; p++) {
            int a = __ldg(rdd + 2 * p), b = __ldg(rdd + 2 * p + 1);
            if (i1 == a && i2 == b) mask_in |= (1u << p);
            if (i1 == a)            mask_fb |= (1u << p);
        }
        unsigned m = mask_in ? mask_in : mask_fb;
        while (m) {
            int p = __ffs(m) - 1; m &= m - 1;
            int slot = atomicAdd(&cnt[p], 1);
            lists[p * MROWS + slot] = tid;
        }
    }
    __syncthreads();
    if (tid == 0) {
        int s = 0;
        #pragma unroll
        for (int p = 0; p < Pk; p++) { goff[p] = s; s += (cnt[p] + GSZ - 1) / GSZ; }
        goff[Pk] = s;
    }
    __syncthreads();

    // ---- patch phase: one warp per (p, group-of-8-rows), f32x2 throughout
    const int ngroups = goff[Pk];
    for (int g = wid; g < ngroups; g += NWARP) {
        int p = 0;
        #pragma unroll
        for (int q = 0; q < Pk - 1; q++) if (g >= goff[q + 1]) p = q + 1;
        const int base = (g - goff[p]) * GSZ;
        const int nv   = min(GSZ, cnt[p] - base);

        int rows[GSZ];
        rows[0] = lists[p * MROWS + base];
        #pragma unroll
        for (int j = 1; j < GSZ; j++)
            rows[j] = (j < nv) ? lists[p * MROWS + base + j] : rows[0];

        const float4* wbase = (const float4*)(Wp1 + (size_t)p * Dk * HPk) + lane;
        u64 hp[GSZ][2];
        #pragma unroll
        for (int j = 0; j < GSZ; j++) { hp[j][0] = 0ull; hp[j][1] = 0ull; }

        #pragma unroll 4
        for (int d = 0; d < Dk; d++) {
            float4 w = __ldg(wbase + d * (HPk / 4));
            u64 w01 = pk2(w.x, w.y), w23 = pk2(w.z, w.w);
            #pragma unroll
            for (int j = 0; j < GSZ; j++) {
                u64 xd = dup2(xs[rows[j] * XSS + d]);   // broadcast LDS
                fma2(hp[j][0], xd, w01);
                fma2(hp[j][1], xd, w23);
            }
        }

        float4 bb = __ldg((const float4*)(bp1 + p * HPk) + lane);
        // Wp2 rows for this lane's 4 HP cols, as natural c-pairs
        u64 wq[4][5];
        #pragma unroll
        for (int q = 0; q < 4; q++) {
            const float2* wr = (const float2*)(Wp2 + ((size_t)p * HPk + lane * 4 + q) * Ck);
            #pragma unroll
            for (int pc = 0; pc < 5; pc++) {
                float2 v = __ldg(wr + pc);
                wq[q][pc] = pk2(v.x, v.y);
            }
        }

        for (int j = 0; j < nv; j++) {
            float2 h01 = upk(hp[j][0]), h23 = upk(hp[j][1]);
            u64 hd[4];
            hd[0] = dup2(fmaxf(h01.x + bb.x, 0.f));
            hd[1] = dup2(fmaxf(h01.y + bb.y, 0.f));
            hd[2] = dup2(fmaxf(h23.x + bb.z, 0.f));
            hd[3] = dup2(fmaxf(h23.y + bb.w, 0.f));
            u64 po[5];
            #pragma unroll
            for (int pc = 0; pc < 5; pc++) po[pc] = 0ull;
            #pragma unroll
            for (int q = 0; q < 4; q++)
                #pragma unroll
                for (int pc = 0; pc < 5; pc++)
                    fma2(po[pc], hd[q], wq[q][pc]);
            #pragma unroll
            for (int pc = 0; pc < 5; pc++) {
                u64 v = po[pc];
                v = add2(v, __shfl_xor_sync(0xffffffffu, v, 16));
                v = add2(v, __shfl_xor_sync(0xffffffffu, v, 8));
                v = add2(v, __shfl_xor_sync(0xffffffffu, v, 4));
                v = add2(v, __shfl_xor_sync(0xffffffffu, v, 2));
                v = add2(v, __shfl_xor_sync(0xffffffffu, v, 1));
                po[pc] = v;
            }
            if (lane == 0) {
                #pragma unroll
                for (int pc = 0; pc < 5; pc++) {
                    float2 v = upk(po[pc]);
                    atomicAdd(&outs[rows[j] * Ck + 2 * pc],
                              v.x + __ldg(bp2 + p * Ck + 2 * pc));
                    atomicAdd(&outs[rows[j] * Ck + 2 * pc + 1],
                              v.y + __ldg(bp2 + p * Ck + 2 * pc + 1));
                }
            }
        }
    }
    __syncthreads();

    // ---- final store
    for (int i = tid; i < MROWS * Ck; i += NT)
        out[(size_t)row0 * Ck + i] = outs[i];
}

extern "C" void kernel_launch(void* const* d_in, const int* in_sizes, int n_in,
                              void* d_out, int out_size)
{
    const float* x   = (const float*)d_in[0];
    const float* Wt1 = (const float*)d_in[1];
    const float* bt1 = (const float*)d_in[2];
    const float* Wt2 = (const float*)d_in[3];
    const float* bt2 = (const float*)d_in[4];
    const float* Wp1 = (const float*)d_in[5];
    const float* bp1 = (const float*)d_in[6];
    const float* Wp2 = (const float*)d_in[7];
    const float* bp2 = (const float*)d_in[8];
    const int*   rdd = (const int*)d_in[9];
    float* out = (float*)d_out;

    cudaFuncSetAttribute(netsum_kernel,
                         cudaFuncAttributeMaxDynamicSharedMemorySize, SMEM_BYTES);
    netsum_kernel<<<BT / MROWS, NT, SMEM_BYTES>>>(
        x, Wt1, bt1, Wt2, bt2, Wp1, bp1, Wp2, bp2, rdd, out);
}

// round 9
// speedup vs baseline: 1.7347x; 1.1155x over previous
#include <cuda_runtime.h>
#include <cstdint>

// ---------------- problem constants ----------------
#define BT   65536
#define Dk   256
#define Hk   512
#define Ck   10
#define Pk   10
#define HPk  128

#define MROWS 128          // rows per CTA
#define NT    512
#define NWARP 16
#define KSLAB 64           // k rows staged per slab (4 slabs per hc)
#define XSS   260          // xs row stride (floats), 16B-aligned
#define GSZ   8            // patch rows per warp-group

// ---------------- smem layout (floats, then ints) ----------------
#define XS_F    (MROWS * XSS)        // 33280
#define WS_F    (KSLAB * 128)        // 8192
#define W2P_F   (5 * 512 * 2)       // 5120 floats (u64 pairs [pc][h])
#define OUTS_F  (MROWS * Ck)         // 1280
#define SMEM_FLOATS (XS_F + WS_F + W2P_F + OUTS_F)
#define SMEM_INTS   (Pk * MROWS + Pk + (Pk + 1))
#define SMEM_BYTES  ((SMEM_FLOATS + SMEM_INTS) * 4)

typedef unsigned long long u64;

// ---------------- f32x2 helpers (FFMA2 path) ----------------
__device__ __forceinline__ u64 pk2(float a, float b) {
    u64 r; asm("mov.b64 %0, {%1, %2};" : "=l"(r) : "f"(a), "f"(b)); return r;
}
__device__ __forceinline__ u64 dup2(float a) { return pk2(a, a); }
__device__ __forceinline__ float2 upk(u64 v) {
    float2 f; asm("mov.b64 {%0, %1}, %2;" : "=f"(f.x), "=f"(f.y) : "l"(v)); return f;
}
__device__ __forceinline__ void fma2(u64& d, u64 a, u64 b) {
    asm("fma.rn.f32x2 %0, %1, %2, %0;" : "+l"(d) : "l"(a), "l"(b));
}
__device__ __forceinline__ u64 add2(u64 a, u64 b) {
    u64 r; asm("add.rn.f32x2 %0, %1, %2;" : "=l"(r) : "l"(a), "l"(b)); return r;
}

__global__ void __launch_bounds__(NT)
netsum_kernel(const float* __restrict__ x,
              const float* __restrict__ Wt1, const float* __restrict__ bt1,
              const float* __restrict__ Wt2, const float* __restrict__ bt2,
              const float* __restrict__ Wp1, const float* __restrict__ bp1,
              const float* __restrict__ Wp2, const float* __restrict__ bp2,
              const int*   __restrict__ rdd,
              float* __restrict__ out)
{
    extern __shared__ float smem[];
    float* xs    = smem;                       // [MROWS][XSS] row-major x tile
    float* ws    = xs + XS_F;                  // [KSLAB][128] Wt1 slab
    u64*   w2p   = (u64*)(ws + WS_F);          // [5][512] packed Wt2 col-pairs
    float* outs  = (float*)(w2p + 5 * 512) ;   // [MROWS][Ck]
    int*   lists = (int*)(outs + OUTS_F);      // [Pk][MROWS]
    int*   cnt   = lists + Pk * MROWS;         // [Pk]
    int*   goff  = cnt + Pk;                   // [Pk+1]

    const int tid  = threadIdx.x;
    const int wid  = tid >> 5;
    const int lane = tid & 31;
    const int row0 = blockIdx.x * MROWS;

    // ---- x tile copy (row-major)
    {
        const int r = tid >> 2, seg = tid & 3;
        const float4* src = (const float4*)(x + (size_t)(row0 + r) * Dk + seg * 64);
        float4* dst = (float4*)(xs + r * XSS + seg * 64);
        #pragma unroll
        for (int i = 0; i < 16; i++) dst[i] = __ldg(src + i);
    }
    // ---- Wt2 -> packed f32x2 smem: w2p[pc*512 + h] = (Wt2[h][2pc], Wt2[h][2pc+1])
    for (int i = tid; i < 5 * 512; i += NT) {
        const int h = i & 511, pc = i >> 9;
        float2 v = __ldg((const float2*)(Wt2 + (size_t)h * Ck) + pc);
        w2p[pc * 512 + h] = pk2(v.x, v.y);
    }
    if (tid < Pk) cnt[tid] = 0;
    __syncthreads();

    // ---- fused GEMM1 + GEMM2 partials ----
    const int ty = tid >> 4;   // 0..31 -> rows ty*4..+3
    const int tx = tid & 15;   // cols {4tx + 64jp + q}

    u64 pout[4][5];
    #pragma unroll
    for (int i = 0; i < 4; i++)
        #pragma unroll
        for (int pc = 0; pc < 5; pc++) pout[i][pc] = 0ull;

    #pragma unroll 1
    for (int hc = 0; hc < 4; hc++) {
        u64 acc[4][2][2];
        #pragma unroll
        for (int jp = 0; jp < 2; jp++) {
            float4 bv = __ldg((const float4*)(bt1 + hc * 128 + 64 * jp) + tx);
            u64 p0 = pk2(bv.x, bv.y), p1 = pk2(bv.z, bv.w);
            #pragma unroll
            for (int i = 0; i < 4; i++) { acc[i][jp][0] = p0; acc[i][jp][1] = p1; }
        }

        #pragma unroll 1
        for (int k0 = 0; k0 < Dk; k0 += KSLAB) {
            __syncthreads();
            {   // stage Wt1[k0..k0+63][hc*128..+128): thread -> (kk=tid>>3, 16 floats)
                const int kk = tid >> 3, sg = tid & 7;
                const float4* src = (const float4*)(Wt1 + (size_t)(k0 + kk) * Hk
                                                    + hc * 128 + sg * 16);
                float4* dst = (float4*)(ws + kk * 128 + sg * 16);
                dst[0] = __ldg(src + 0);
                dst[1] = __ldg(src + 1);
                dst[2] = __ldg(src + 2);
                dst[3] = __ldg(src + 3);
            }
            __syncthreads();

            #pragma unroll 2
            for (int kk = 0; kk < KSLAB; kk += 4) {
                float4 a[4];
                #pragma unroll
                for (int i = 0; i < 4; i++)
                    a[i] = *(const float4*)(xs + (ty * 4 + i) * XSS + k0 + kk);
                #pragma unroll
                for (int kq = 0; kq < 4; kq++) {
                    u64 b[2][2];
                    #pragma unroll
                    for (int jp = 0; jp < 2; jp++) {
                        float4 w = *(const float4*)(ws + (kk + kq) * 128 + 4 * tx + 64 * jp);
                        b[jp][0] = pk2(w.x, w.y);
                        b[jp][1] = pk2(w.z, w.w);
                    }
                    #pragma unroll
                    for (int i = 0; i < 4; i++) {
                        const float av = (kq == 0) ? a[i].x : (kq == 1) ? a[i].y
                                       : (kq == 2) ? a[i].z : a[i].w;
                        u64 ad = dup2(av);
                        #pragma unroll
                        for (int jp = 0; jp < 2; jp++) {
                            fma2(acc[i][jp][0], ad, b[jp][0]);
                            fma2(acc[i][jp][1], ad, b[jp][1]);
                        }
                    }
                }
            }
        }

        // GEMM2 partials: relu(acc) @ Wt2 (packed pairs from smem)
        #pragma unroll
        for (int jp = 0; jp < 2; jp++)
            #pragma unroll
            for (int q = 0; q < 4; q++) {
                const int hg = hc * 128 + 4 * tx + 64 * jp + q;
                u64 wv[5];
                #pragma unroll
                for (int pc = 0; pc < 5; pc++) wv[pc] = w2p[pc * 512 + hg];
                #pragma unroll
                for (int i = 0; i < 4; i++) {
                    float2 pr = upk(acc[i][jp][q >> 1]);
                    float hv = fmaxf((q & 1) ? pr.y : pr.x, 0.f);
                    u64 hd = dup2(hv);
                    #pragma unroll
                    for (int pc = 0; pc < 5; pc++) fma2(pout[i][pc], hd, wv[pc]);
                }
            }
    }

    // ---- reduce pout across the 16 tx lanes
    #pragma unroll
    for (int i = 0; i < 4; i++)
        #pragma unroll
        for (int pc = 0; pc < 5; pc++) {
            u64 v = pout[i][pc];
            v = add2(v, __shfl_xor_sync(0xffffffffu, v, 8));
            v = add2(v, __shfl_xor_sync(0xffffffffu, v, 4));
            v = add2(v, __shfl_xor_sync(0xffffffffu, v, 2));
            v = add2(v, __shfl_xor_sync(0xffffffffu, v, 1));
            pout[i][pc] = v;
        }
    if (tx == 0) {
        #pragma unroll
        for (int i = 0; i < 4; i++)
            #pragma unroll
            for (int pc = 0; pc < 5; pc++) {
                float2 v = upk(pout[i][pc]);
                outs[(ty * 4 + i) * Ck + 2 * pc]     = v.x + __ldg(bt2 + 2 * pc);
                outs[(ty * 4 + i) * Ck + 2 * pc + 1] = v.y + __ldg(bt2 + 2 * pc + 1);
            }
    }
    __syncthreads();

    // ---- top-2 (JAX tie semantics), bitmap, per-p worklists
    if (tid < MROWS) {
        float v[Ck];
        #pragma unroll
        for (int c = 0; c < Ck; c++) v[c] = outs[tid * Ck + c];
        int i1 = 0; float m1 = v[0];
        #pragma unroll
        for (int c = 1; c < Ck; c++) if (v[c] > m1) { m1 = v[c]; i1 = c; }
        int i2 = -1; float m2 = -3.0e38f;
        #pragma unroll
        for (int c = 0; c < Ck; c++)
            if (c != i1 && v[c] > m2) { m2 = v[c]; i2 = c; }

        unsigned mask_in = 0u, mask_fb = 0u;
        #pragma unroll
        for (int p = 0; p < Pk; p++) {
            int a = __ldg(rdd + 2 * p), b = __ldg(rdd + 2 * p + 1);
            if (i1 == a && i2 == b) mask_in |= (1u << p);
            if (i1 == a)            mask_fb |= (1u << p);
        }
        unsigned m = mask_in ? mask_in : mask_fb;
        while (m) {
            int p = __ffs(m) - 1; m &= m - 1;
            int slot = atomicAdd(&cnt[p], 1);
            lists[p * MROWS + slot] = tid;
        }
    }
    __syncthreads();
    if (tid == 0) {
        int s = 0;
        #pragma unroll
        for (int p = 0; p < Pk; p++) { goff[p] = s; s += (cnt[p] + GSZ - 1) / GSZ; }
        goff[Pk] = s;
    }
    __syncthreads();

    // ---- patch phase: one warp per (p, group-of-8-rows), f32x2 + LDS.128 x
    const int ngroups = goff[Pk];
    for (int g = wid; g < ngroups; g += NWARP) {
        int p = 0;
        #pragma unroll
        for (int q = 0; q < Pk - 1; q++) if (g >= goff[q + 1]) p = q + 1;
        const int base = (g - goff[p]) * GSZ;
        const int nv   = min(GSZ, cnt[p] - base);

        int rows[GSZ];
        rows[0] = lists[p * MROWS + base];
        #pragma unroll
        for (int j = 1; j < GSZ; j++)
            rows[j] = (j < nv) ? lists[p * MROWS + base + j] : rows[0];

        const float4* wbase = (const float4*)(Wp1 + (size_t)p * Dk * HPk) + lane;
        u64 hp[GSZ][2];
        #pragma unroll
        for (int j = 0; j < GSZ; j++) { hp[j][0] = 0ull; hp[j][1] = 0ull; }

        #pragma unroll 2
        for (int d = 0; d < Dk; d += 4) {
            float4 w0 = __ldg(wbase + (d + 0) * 32);
            float4 w1 = __ldg(wbase + (d + 1) * 32);
            float4 w2 = __ldg(wbase + (d + 2) * 32);
            float4 w3 = __ldg(wbase + (d + 3) * 32);
            u64 wp0a = pk2(w0.x, w0.y), wp0b = pk2(w0.z, w0.w);
            u64 wp1a = pk2(w1.x, w1.y), wp1b = pk2(w1.z, w1.w);
            u64 wp2a = pk2(w2.x, w2.y), wp2b = pk2(w2.z, w2.w);
            u64 wp3a = pk2(w3.x, w3.y), wp3b = pk2(w3.z, w3.w);
            #pragma unroll
            for (int j = 0; j < GSZ; j++) {
                float4 xq = *(const float4*)(xs + rows[j] * XSS + d);  // broadcast LDS.128
                u64 x0 = dup2(xq.x), x1 = dup2(xq.y), x2 = dup2(xq.z), x3 = dup2(xq.w);
                fma2(hp[j][0], x0, wp0a); fma2(hp[j][1], x0, wp0b);
                fma2(hp[j][0], x1, wp1a); fma2(hp[j][1], x1, wp1b);
                fma2(hp[j][0], x2, wp2a); fma2(hp[j][1], x2, wp2b);
                fma2(hp[j][0], x3, wp3a); fma2(hp[j][1], x3, wp3b);
            }
        }

        float4 bb = __ldg((const float4*)(bp1 + p * HPk) + lane);
        u64 wq[4][5];
        #pragma unroll
        for (int q = 0; q < 4; q++) {
            const float2* wr = (const float2*)(Wp2 + ((size_t)p * HPk + lane * 4 + q) * Ck);
            #pragma unroll
            for (int pc = 0; pc < 5; pc++) {
                float2 v = __ldg(wr + pc);
                wq[q][pc] = pk2(v.x, v.y);
            }
        }

        for (int j = 0; j < nv; j++) {
            float2 h01 = upk(hp[j][0]), h23 = upk(hp[j][1]);
            u64 hd[4];
            hd[0] = dup2(fmaxf(h01.x + bb.x, 0.f));
            hd[1] = dup2(fmaxf(h01.y + bb.y, 0.f));
            hd[2] = dup2(fmaxf(h23.x + bb.z, 0.f));
            hd[3] = dup2(fmaxf(h23.y + bb.w, 0.f));
            u64 po[5];
            #pragma unroll
            for (int pc = 0; pc < 5; pc++) po[pc] = 0ull;
            #pragma unroll
            for (int q = 0; q < 4; q++)
                #pragma unroll
                for (int pc = 0; pc < 5; pc++)
                    fma2(po[pc], hd[q], wq[q][pc]);
            #pragma unroll
            for (int pc = 0; pc < 5; pc++) {
                u64 v = po[pc];
                v = add2(v, __shfl_xor_sync(0xffffffffu, v, 16));
                v = add2(v, __shfl_xor_sync(0xffffffffu, v, 8));
                v = add2(v, __shfl_xor_sync(0xffffffffu, v, 4));
                v = add2(v, __shfl_xor_sync(0xffffffffu, v, 2));
                v = add2(v, __shfl_xor_sync(0xffffffffu, v, 1));
                po[pc] = v;
            }
            if (lane == 0) {
                #pragma unroll
                for (int pc = 0; pc < 5; pc++) {
                    float2 v = upk(po[pc]);
                    atomicAdd(&outs[rows[j] * Ck + 2 * pc],
                              v.x + __ldg(bp2 + p * Ck + 2 * pc));
                    atomicAdd(&outs[rows[j] * Ck + 2 * pc + 1],
                              v.y + __ldg(bp2 + p * Ck + 2 * pc + 1));
                }
            }
        }
    }
    __syncthreads();

    // ---- final store
    for (int i = tid; i < MROWS * Ck; i += NT)
        out[(size_t)row0 * Ck + i] = outs[i];
}

extern "C" void kernel_launch(void* const* d_in, const int* in_sizes, int n_in,
                              void* d_out, int out_size)
{
    const float* x   = (const float*)d_in[0];
    const float* Wt1 = (const float*)d_in[1];
    const float* bt1 = (const float*)d_in[2];
    const float* Wt2 = (const float*)d_in[3];
    const float* bt2 = (const float*)d_in[4];
    const float* Wp1 = (const float*)d_in[5];
    const float* bp1 = (const float*)d_in[6];
    const float* Wp2 = (const float*)d_in[7];
    const float* bp2 = (const float*)d_in[8];
    const int*   rdd = (const int*)d_in[9];
    float* out = (float*)d_out;

    cudaFuncSetAttribute(netsum_kernel,
                         cudaFuncAttributeMaxDynamicSharedMemorySize, SMEM_BYTES);
    netsum_kernel<<<BT / MROWS, NT, SMEM_BYTES>>>(
        x, Wt1, bt1, Wt2, bt2, Wp1, bp1, Wp2, bp2, rdd, out);
}

// round 11
// speedup vs baseline: 1.8223x; 1.0505x over previous
#include <cuda_runtime.h>
#include <cstdint>

// ---------------- problem constants ----------------
#define BT   65536
#define Dk   256
#define Hk   512
#define Ck   10
#define Pk   10
#define HPk  128

#define MROWS 128          // rows per CTA
#define NT    512
#define NWARP 16
#define KSLAB 32           // k rows per pipeline stage
#define NSTAGE 32          // 4 hc x 8 ks
#define XSS   260          // xs row stride (floats), 16B-aligned
#define GSZ   8            // patch rows per warp-group

// ---------------- smem layout (floats, then ints) ----------------
#define XS_F    (MROWS * XSS)        // 33280
#define WS_F    (3 * KSLAB * 128)    // 12288 (triple-buffered slab ring)
#define W2P_F   (5 * 512 * 2)        // 5120 floats (u64 pairs [pc][h])
#define OUTS_F  (MROWS * Ck)         // 1280
#define SMEM_FLOATS (XS_F + WS_F + W2P_F + OUTS_F)
#define SMEM_INTS   (Pk * MROWS + Pk + (Pk + 1))
#define SMEM_BYTES  ((SMEM_FLOATS + SMEM_INTS) * 4)

typedef unsigned long long u64;

// ---------------- f32x2 helpers (FFMA2 path) ----------------
__device__ __forceinline__ u64 pk2(float a, float b) {
    u64 r; asm("mov.b64 %0, {%1, %2};" : "=l"(r) : "f"(a), "f"(b)); return r;
}
__device__ __forceinline__ u64 dup2(float a) { return pk2(a, a); }
__device__ __forceinline__ float2 upk(u64 v) {
    float2 f; asm("mov.b64 {%0, %1}, %2;" : "=f"(f.x), "=f"(f.y) : "l"(v)); return f;
}
__device__ __forceinline__ void fma2(u64& d, u64 a, u64 b) {
    asm("fma.rn.f32x2 %0, %1, %2, %0;" : "+l"(d) : "l"(a), "l"(b));
}
__device__ __forceinline__ u64 add2(u64 a, u64 b) {
    u64 r; asm("add.rn.f32x2 %0, %1, %2;" : "=l"(r) : "l"(a), "l"(b)); return r;
}

// ---------------- cp.async helpers ----------------
__device__ __forceinline__ uint32_t smem_u32(const void* p) {
    uint32_t a;
    asm("{ .reg .u64 t; cvta.to.shared.u64 t, %1; cvt.u32.u64 %0, t; }" : "=r"(a) : "l"(p));
    return a;
}
__device__ __forceinline__ void cp16(uint32_t dst, const void* src) {
    asm volatile("cp.async.cg.shared.global [%0], [%1], 16;" :: "r"(dst), "l"(src) : "memory");
}
#define CP_COMMIT() asm volatile("cp.async.commit_group;" ::: "memory")
#define CP_WAIT1()  asm volatile("cp.async.wait_group 1;" ::: "memory")

__global__ void __launch_bounds__(NT)
netsum_kernel(const float* __restrict__ x,
              const float* __restrict__ Wt1, const float* __restrict__ bt1,
              const float* __restrict__ Wt2, const float* __restrict__ bt2,
              const float* __restrict__ Wp1, const float* __restrict__ bp1,
              const float* __restrict__ Wp2, const float* __restrict__ bp2,
              const int*   __restrict__ rdd,
              float* __restrict__ out)
{
    extern __shared__ float smem[];
    float* xs    = smem;                       // [MROWS][XSS] row-major x tile
    float* ws    = xs + XS_F;                  // 3 x [KSLAB][128] Wt1 slab ring
    u64*   w2p   = (u64*)(ws + WS_F);          // [5][512] packed Wt2 col-pairs
    float* outs  = (float*)(w2p + 5 * 512);    // [MROWS][Ck]
    int*   lists = (int*)(outs + OUTS_F);      // [Pk][MROWS]
    int*   cnt   = lists + Pk * MROWS;         // [Pk]
    int*   goff  = cnt + Pk;                   // [Pk+1]

    const int tid  = threadIdx.x;
    const int wid  = tid >> 5;
    const int lane = tid & 31;
    const int row0 = blockIdx.x * MROWS;

    // per-thread staging map: kk = tid>>4 (0..31), sg = tid&15 (8 floats = 32B)
    const int st_kk = tid >> 4, st_sg = tid & 15;
    const uint32_t ws_base = smem_u32(ws);
    const uint32_t st_dst  = ws_base + (uint32_t)(st_kk * 128 + st_sg * 8) * 4;

    // ---- issue stage 0 prefetch immediately
    {
        const float* src = Wt1 + (size_t)st_kk * Hk + st_sg * 8;   // hc=0, k0=0
        cp16(st_dst, src);
        cp16(st_dst + 16, (const char*)src + 16);
    }
    CP_COMMIT();

    // ---- x tile copy (row-major)
    {
        const int r = tid >> 2, seg = tid & 3;
        const float4* src = (const float4*)(x + (size_t)(row0 + r) * Dk + seg * 64);
        float4* dst = (float4*)(xs + r * XSS + seg * 64);
        #pragma unroll
        for (int i = 0; i < 16; i++) dst[i] = __ldg(src + i);
    }
    // ---- Wt2 -> packed f32x2 smem
    for (int i = tid; i < 5 * 512; i += NT) {
        const int h = i & 511, pc = i >> 9;
        float2 v = __ldg((const float2*)(Wt2 + (size_t)h * Ck) + pc);
        w2p[pc * 512 + h] = pk2(v.x, v.y);
    }
    if (tid < Pk) cnt[tid] = 0;

    // ---- fused GEMM1 + GEMM2 partials, cp.async pipelined ----
    const int ty = tid >> 4;   // 0..31 -> rows ty*4..+3
    const int tx = tid & 15;   // cols {4tx + 64jp + q}

    u64 pout[4][5];
    #pragma unroll
    for (int i = 0; i < 4; i++)
        #pragma unroll
        for (int pc = 0; pc < 5; pc++) pout[i][pc] = 0ull;

    u64 acc[4][2][2];

    #pragma unroll 1
    for (int s = 0; s < NSTAGE; s++) {
        const int hc = s >> 3, ks = s & 7;
        // issue prefetch for stage s+1 into buffer (s+1)%3
        if (s + 1 < NSTAGE) {
            const int nhc = (s + 1) >> 3, nks = (s + 1) & 7;
            const float* src = Wt1 + (size_t)(nks * KSLAB + st_kk) * Hk
                             + nhc * 128 + st_sg * 8;
            const uint32_t dst = st_dst + (uint32_t)(((s + 1) % 3) * KSLAB * 128) * 4;
            cp16(dst, src);
            cp16(dst + 16, (const char*)src + 16);
        }
        CP_COMMIT();
        CP_WAIT1();
        __syncthreads();

        if (ks == 0) {   // init acc with bias for this hc
            #pragma unroll
            for (int jp = 0; jp < 2; jp++) {
                float4 bv = __ldg((const float4*)(bt1 + hc * 128 + 64 * jp) + tx);
                u64 p0 = pk2(bv.x, bv.y), p1 = pk2(bv.z, bv.w);
                #pragma unroll
                for (int i = 0; i < 4; i++) { acc[i][jp][0] = p0; acc[i][jp][1] = p1; }
            }
        }

        const float* wsb = ws + (s % 3) * KSLAB * 128;
        const int kbase = ks * KSLAB;
        #pragma unroll 4
        for (int kk = 0; kk < KSLAB; kk += 4) {
            float4 a[4];
            #pragma unroll
            for (int i = 0; i < 4; i++)
                a[i] = *(const float4*)(xs + (ty * 4 + i) * XSS + kbase + kk);
            #pragma unroll
            for (int kq = 0; kq < 4; kq++) {
                u64 b[2][2];
                #pragma unroll
                for (int jp = 0; jp < 2; jp++) {
                    float4 w = *(const float4*)(wsb + (kk + kq) * 128 + 4 * tx + 64 * jp);
                    b[jp][0] = pk2(w.x, w.y);
                    b[jp][1] = pk2(w.z, w.w);
                }
                #pragma unroll
                for (int i = 0; i < 4; i++) {
                    const float av = (kq == 0) ? a[i].x : (kq == 1) ? a[i].y
                                   : (kq == 2) ? a[i].z : a[i].w;
                    u64 ad = dup2(av);
                    #pragma unroll
                    for (int jp = 0; jp < 2; jp++) {
                        fma2(acc[i][jp][0], ad, b[jp][0]);
                        fma2(acc[i][jp][1], ad, b[jp][1]);
                    }
                }
            }
        }

        if (ks == 7) {   // GEMM2 partials for this hc (overlaps next prefetch)
            #pragma unroll
            for (int jp = 0; jp < 2; jp++)
                #pragma unroll
                for (int q = 0; q < 4; q++) {
                    const int hg = hc * 128 + 4 * tx + 64 * jp + q;
                    u64 wv[5];
                    #pragma unroll
                    for (int pc = 0; pc < 5; pc++) wv[pc] = w2p[pc * 512 + hg];
                    #pragma unroll
                    for (int i = 0; i < 4; i++) {
                        float2 pr = upk(acc[i][jp][q >> 1]);
                        float hv = fmaxf((q & 1) ? pr.y : pr.x, 0.f);
                        u64 hd = dup2(hv);
                        #pragma unroll
                        for (int pc = 0; pc < 5; pc++) fma2(pout[i][pc], hd, wv[pc]);
                    }
                }
        }
    }

    // ---- reduce pout across the 16 tx lanes
    #pragma unroll
    for (int i = 0; i < 4; i++)
        #pragma unroll
        for (int pc = 0; pc < 5; pc++) {
            u64 v = pout[i][pc];
            v = add2(v, __shfl_xor_sync(0xffffffffu, v, 8));
            v = add2(v, __shfl_xor_sync(0xffffffffu, v, 4));
            v = add2(v, __shfl_xor_sync(0xffffffffu, v, 2));
            v = add2(v, __shfl_xor_sync(0xffffffffu, v, 1));
            pout[i][pc] = v;
        }
    if (tx == 0) {
        #pragma unroll
        for (int i = 0; i < 4; i++)
            #pragma unroll
            for (int pc = 0; pc < 5; pc++) {
                float2 v = upk(pout[i][pc]);
                outs[(ty * 4 + i) * Ck + 2 * pc]     = v.x + __ldg(bt2 + 2 * pc);
                outs[(ty * 4 + i) * Ck + 2 * pc + 1] = v.y + __ldg(bt2 + 2 * pc + 1);
            }
    }
    __syncthreads();

    // ---- top-2 (JAX tie semantics), bitmap, per-p worklists
    if (tid < MROWS) {
        float v[Ck];
        #pragma unroll
        for (int c = 0; c < Ck; c++) v[c] = outs[tid * Ck + c];
        int i1 = 0; float m1 = v[0];
        #pragma unroll
        for (int c = 1; c < Ck; c++) if (v[c] > m1) { m1 = v[c]; i1 = c; }
        int i2 = -1; float m2 = -3.0e38f;
        #pragma unroll
        for (int c = 0; c < Ck; c++)
            if (c != i1 && v[c] > m2) { m2 = v[c]; i2 = c; }

        unsigned mask_in = 0u, mask_fb = 0u;
        #pragma unroll
        for (int p = 0; p < Pk; p++) {
            int a = __ldg(rdd + 2 * p), b = __ldg(rdd + 2 * p + 1);
            if (i1 == a && i2 == b) mask_in |= (1u << p);
            if (i1 == a)            mask_fb |= (1u << p);
        }
        unsigned m = mask_in ? mask_in : mask_fb;
        while (m) {
            int p = __ffs(m) - 1; m &= m - 1;
            int slot = atomicAdd(&cnt[p], 1);
            lists[p * MROWS + slot] = tid;
        }
    }
    __syncthreads();
    if (tid == 0) {
        int s = 0;
        #pragma unroll
        for (int p = 0; p < Pk; p++) { goff[p] = s; s += (cnt[p] + GSZ - 1) / GSZ; }
        goff[Pk] = s;
    }
    __syncthreads();

    // ---- patch phase: one warp per (p, group-of-8-rows), f32x2 + LDS.128 x
    const int ngroups = goff[Pk];
    for (int g = wid; g < ngroups; g += NWARP) {
        int p = 0;
        #pragma unroll
        for (int q = 0; q < Pk - 1; q++) if (g >= goff[q + 1]) p = q + 1;
        const int base = (g - goff[p]) * GSZ;
        const int nv   = min(GSZ, cnt[p] - base);

        int rows[GSZ];
        rows[0] = lists[p * MROWS + base];
        #pragma unroll
        for (int j = 1; j < GSZ; j++)
            rows[j] = (j < nv) ? lists[p * MROWS + base + j] : rows[0];

        const float4* wbase = (const float4*)(Wp1 + (size_t)p * Dk * HPk) + lane;
        u64 hp[GSZ][2];
        #pragma unroll
        for (int j = 0; j < GSZ; j++) { hp[j][0] = 0ull; hp[j][1] = 0ull; }

        #pragma unroll 2
        for (int d = 0; d < Dk; d += 4) {
            float4 w0 = __ldg(wbase + (d + 0) * 32);
            float4 w1 = __ldg(wbase + (d + 1) * 32);
            float4 w2 = __ldg(wbase + (d + 2) * 32);
            float4 w3 = __ldg(wbase + (d + 3) * 32);
            u64 wp0a = pk2(w0.x, w0.y), wp0b = pk2(w0.z, w0.w);
            u64 wp1a = pk2(w1.x, w1.y), wp1b = pk2(w1.z, w1.w);
            u64 wp2a = pk2(w2.x, w2.y), wp2b = pk2(w2.z, w2.w);
            u64 wp3a = pk2(w3.x, w3.y), wp3b = pk2(w3.z, w3.w);
            #pragma unroll
            for (int j = 0; j < GSZ; j++) {
                float4 xq = *(const float4*)(xs + rows[j] * XSS + d);  // broadcast LDS.128
                u64 x0 = dup2(xq.x), x1 = dup2(xq.y), x2 = dup2(xq.z), x3 = dup2(xq.w);
                fma2(hp[j][0], x0, wp0a); fma2(hp[j][1], x0, wp0b);
                fma2(hp[j][0], x1, wp1a); fma2(hp[j][1], x1, wp1b);
                fma2(hp[j][0], x2, wp2a); fma2(hp[j][1], x2, wp2b);
                fma2(hp[j][0], x3, wp3a); fma2(hp[j][1], x3, wp3b);
            }
        }

        float4 bb = __ldg((const float4*)(bp1 + p * HPk) + lane);
        u64 wq[4][5];
        #pragma unroll
        for (int q = 0; q < 4; q++) {
            const float2* wr = (const float2*)(Wp2 + ((size_t)p * HPk + lane * 4 + q) * Ck);
            #pragma unroll
            for (int pc = 0; pc < 5; pc++) {
                float2 v = __ldg(wr + pc);
                wq[q][pc] = pk2(v.x, v.y);
            }
        }

        for (int j = 0; j < nv; j++) {
            float2 h01 = upk(hp[j][0]), h23 = upk(hp[j][1]);
            u64 hd[4];
            hd[0] = dup2(fmaxf(h01.x + bb.x, 0.f));
            hd[1] = dup2(fmaxf(h01.y + bb.y, 0.f));
            hd[2] = dup2(fmaxf(h23.x + bb.z, 0.f));
            hd[3] = dup2(fmaxf(h23.y + bb.w, 0.f));
            u64 po[5];
            #pragma unroll
            for (int pc = 0; pc < 5; pc++) po[pc] = 0ull;
            #pragma unroll
            for (int q = 0; q < 4; q++)
                #pragma unroll
                for (int pc = 0; pc < 5; pc++)
                    fma2(po[pc], hd[q], wq[q][pc]);
            #pragma unroll
            for (int pc = 0; pc < 5; pc++) {
                u64 v = po[pc];
                v = add2(v, __shfl_xor_sync(0xffffffffu, v, 16));
                v = add2(v, __shfl_xor_sync(0xffffffffu, v, 8));
                v = add2(v, __shfl_xor_sync(0xffffffffu, v, 4));
                v = add2(v, __shfl_xor_sync(0xffffffffu, v, 2));
                v = add2(v, __shfl_xor_sync(0xffffffffu, v, 1));
                po[pc] = v;
            }
            if (lane == 0) {
                #pragma unroll
                for (int pc = 0; pc < 5; pc++) {
                    float2 v = upk(po[pc]);
                    atomicAdd(&outs[rows[j] * Ck + 2 * pc],
                              v.x + __ldg(bp2 + p * Ck + 2 * pc));
                    atomicAdd(&outs[rows[j] * Ck + 2 * pc + 1],
                              v.y + __ldg(bp2 + p * Ck + 2 * pc + 1));
                }
            }
        }
    }
    __syncthreads();

    // ---- final store
    for (int i = tid; i < MROWS * Ck; i += NT)
        out[(size_t)row0 * Ck + i] = outs[i];
}

extern "C" void kernel_launch(void* const* d_in, const int* in_sizes, int n_in,
                              void* d_out, int out_size)
{
    const float* x   = (const float*)d_in[0];
    const float* Wt1 = (const float*)d_in[1];
    const float* bt1 = (const float*)d_in[2];
    const float* Wt2 = (const float*)d_in[3];
    const float* bt2 = (const float*)d_in[4];
    const float* Wp1 = (const float*)d_in[5];
    const float* bp1 = (const float*)d_in[6];
    const float* Wp2 = (const float*)d_in[7];
    const float* bp2 = (const float*)d_in[8];
    const int*   rdd = (const int*)d_in[9];
    float* out = (float*)d_out;

    cudaFuncSetAttribute(netsum_kernel,
                         cudaFuncAttributeMaxDynamicSharedMemorySize, SMEM_BYTES);
    netsum_kernel<<<BT / MROWS, NT, SMEM_BYTES>>>(
        x, Wt1, bt1, Wt2, bt2, Wp1, bp1, Wp2, bp2, rdd, out);
}

// round 14
// speedup vs baseline: 1.8290x; 1.0037x over previous
#include <cuda_runtime.h>
#include <cstdint>

// ---------------- problem constants ----------------
#define BT   65536
#define Dk   256
#define Hk   512
#define Ck   10
#define Pk   10
#define HPk  128

#define MROWS 64           // rows per CTA
#define NT    256
#define NWARP 8
#define KSLAB 16           // k rows per pipeline stage
#define NSTAGE 64          // 4 hc x 16 ks
#define XSS   260          // xs row stride (floats), 16B-aligned
#define GSZ   8            // patch rows per warp-group

// ---------------- smem layout (floats, then ints) ----------------
#define XS_F    (MROWS * XSS)        // 16640
#define WS_F    (2 * KSLAB * 128)    // 4096 (double-buffered slab ring)
#define W2P_F   (5 * 512 * 2)        // 5120 floats (u64 pairs [pc][h])
#define OUTS_F  (MROWS * Ck)         // 640
#define SMEM_FLOATS (XS_F + WS_F + W2P_F + OUTS_F)
#define SMEM_INTS   (Pk * MROWS + Pk + (Pk + 1))
#define SMEM_BYTES  ((SMEM_FLOATS + SMEM_INTS) * 4)

typedef unsigned long long u64;

// ---------------- f32x2 helpers (FFMA2 path) ----------------
__device__ __forceinline__ u64 pk2(float a, float b) {
    u64 r; asm("mov.b64 %0, {%1, %2};" : "=l"(r) : "f"(a), "f"(b)); return r;
}
__device__ __forceinline__ u64 dup2(float a) { return pk2(a, a); }
__device__ __forceinline__ float2 upk(u64 v) {
    float2 f; asm("mov.b64 {%0, %1}, %2;" : "=f"(f.x), "=f"(f.y) : "l"(v)); return f;
}
__device__ __forceinline__ void fma2(u64& d, u64 a, u64 b) {
    asm("fma.rn.f32x2 %0, %1, %2, %0;" : "+l"(d) : "l"(a), "l"(b));
}
__device__ __forceinline__ u64 add2(u64 a, u64 b) {
    u64 r; asm("add.rn.f32x2 %0, %1, %2;" : "=l"(r) : "l"(a), "l"(b)); return r;
}

// ---------------- cp.async helpers ----------------
__device__ __forceinline__ uint32_t smem_u32(const void* p) {
    uint32_t a;
    asm("{ .reg .u64 t; cvta.to.shared.u64 t, %1; cvt.u32.u64 %0, t; }" : "=r"(a) : "l"(p));
    return a;
}
__device__ __forceinline__ void cp16(uint32_t dst, const void* src) {
    asm volatile("cp.async.cg.shared.global [%0], [%1], 16;" :: "r"(dst), "l"(src) : "memory");
}
#define CP_COMMIT() asm volatile("cp.async.commit_group;" ::: "memory")
#define CP_WAIT0()  asm volatile("cp.async.wait_group 0;" ::: "memory")

__global__ void __launch_bounds__(NT, 2)
netsum_kernel(const float* __restrict__ x,
              const float* __restrict__ Wt1, const float* __restrict__ bt1,
              const float* __restrict__ Wt2, const float* __restrict__ bt2,
              const float* __restrict__ Wp1, const float* __restrict__ bp1,
              const float* __restrict__ Wp2, const float* __restrict__ bp2,
              const int*   __restrict__ rdd,
              float* __restrict__ out)
{
    extern __shared__ float smem[];
    float* xs    = smem;                       // [MROWS][XSS] row-major x tile
    float* ws    = xs + XS_F;                  // 2 x [KSLAB][128] Wt1 slab ring
    u64*   w2p   = (u64*)(ws + WS_F);          // [5][512] packed Wt2 col-pairs
    float* outs  = (float*)(w2p + 5 * 512);    // [MROWS][Ck]
    int*   lists = (int*)(outs + OUTS_F);      // [Pk][MROWS]
    int*   cnt   = lists + Pk * MROWS;         // [Pk]
    int*   goff  = cnt + Pk;                   // [Pk+1]

    const int tid  = threadIdx.x;
    const int wid  = tid >> 5;
    const int lane = tid & 31;
    const int row0 = blockIdx.x * MROWS;

    // staging map: kk = tid>>4 (0..15), sg = tid&15 (8 floats = 32B per thread)
    const int st_kk = tid >> 4, st_sg = tid & 15;
    const uint32_t ws_base = smem_u32(ws);
    const uint32_t st_dst  = ws_base + (uint32_t)(st_kk * 128 + st_sg * 8) * 4;

    // ---- issue stage 0 prefetch immediately (hc=0, k rows 0..15)
    {
        const float* src = Wt1 + (size_t)st_kk * Hk + st_sg * 8;
        cp16(st_dst, src);
        cp16(st_dst + 16, (const char*)src + 16);
    }
    CP_COMMIT();

    // ---- x tile copy (row-major) — overlaps stage-0 fetch
    {
        const int r = tid >> 2, seg = tid & 3;
        const float4* src = (const float4*)(x + (size_t)(row0 + r) * Dk + seg * 64);
        float4* dst = (float4*)(xs + r * XSS + seg * 64);
        #pragma unroll
        for (int i = 0; i < 16; i++) dst[i] = __ldg(src + i);
    }
    // ---- Wt2 -> packed f32x2 smem
    for (int i = tid; i < 5 * 512; i += NT) {
        const int h = i & 511, pc = i >> 9;
        float2 v = __ldg((const float2*)(Wt2 + (size_t)h * Ck) + pc);
        w2p[pc * 512 + h] = pk2(v.x, v.y);
    }
    if (tid < Pk) cnt[tid] = 0;

    // ---- fused GEMM1 + GEMM2 partials, cp.async pipelined ----
    const int ty = tid >> 4;   // 0..15 -> rows ty*4..+3
    const int tx = tid & 15;   // cols {4tx + 64jp + q}

    u64 pout[4][5];
    #pragma unroll
    for (int i = 0; i < 4; i++)
        #pragma unroll
        for (int pc = 0; pc < 5; pc++) pout[i][pc] = 0ull;

    u64 acc[4][2][2];

    #pragma unroll 1
    for (int s = 0; s < NSTAGE; s++) {
        const int hc = s >> 4, ks = s & 15;

        // stage-s data must have landed; barrier also proves all warps are
        // done reading buffer (s+1)%2 (their stage s-1 compute) -> WAR-safe.
        CP_WAIT0();
        __syncthreads();

        // issue prefetch for stage s+1 into buffer (s+1)%2 (safe: after barrier)
        if (s + 1 < NSTAGE) {
            const int nhc = (s + 1) >> 4, nks = (s + 1) & 15;
            const float* src = Wt1 + (size_t)(nks * KSLAB + st_kk) * Hk
                             + nhc * 128 + st_sg * 8;
            const uint32_t dst = st_dst + (uint32_t)(((s + 1) & 1) * KSLAB * 128) * 4;
            cp16(dst, src);
            cp16(dst + 16, (const char*)src + 16);
            CP_COMMIT();
        }

        if (ks == 0) {   // init acc with bias for this hc
            #pragma unroll
            for (int jp = 0; jp < 2; jp++) {
                float4 bv = __ldg((const float4*)(bt1 + hc * 128 + 64 * jp) + tx);
                u64 p0 = pk2(bv.x, bv.y), p1 = pk2(bv.z, bv.w);
                #pragma unroll
                for (int i = 0; i < 4; i++) { acc[i][jp][0] = p0; acc[i][jp][1] = p1; }
            }
        }

        const float* wsb = ws + (s & 1) * KSLAB * 128;
        const int kbase = ks * KSLAB;
        #pragma unroll 4
        for (int kk = 0; kk < KSLAB; kk += 4) {
            float4 a[4];
            #pragma unroll
            for (int i = 0; i < 4; i++)
                a[i] = *(const float4*)(xs + (ty * 4 + i) * XSS + kbase + kk);
            #pragma unroll
            for (int kq = 0; kq < 4; kq++) {
                u64 b[2][2];
                #pragma unroll
                for (int jp = 0; jp < 2; jp++) {
                    float4 w = *(const float4*)(wsb + (kk + kq) * 128 + 4 * tx + 64 * jp);
                    b[jp][0] = pk2(w.x, w.y);
                    b[jp][1] = pk2(w.z, w.w);
                }
                #pragma unroll
                for (int i = 0; i < 4; i++) {
                    const float av = (kq == 0) ? a[i].x : (kq == 1) ? a[i].y
                                   : (kq == 2) ? a[i].z : a[i].w;
                    u64 ad = dup2(av);
                    #pragma unroll
                    for (int jp = 0; jp < 2; jp++) {
                        fma2(acc[i][jp][0], ad, b[jp][0]);
                        fma2(acc[i][jp][1], ad, b[jp][1]);
                    }
                }
            }
        }

        if (ks == 15) {   // GEMM2 partials for this hc (overlaps next prefetch)
            #pragma unroll
            for (int jp = 0; jp < 2; jp++)
                #pragma unroll
                for (int q = 0; q < 4; q++) {
                    const int hg = hc * 128 + 4 * tx + 64 * jp + q;
                    u64 wv[5];
                    #pragma unroll
                    for (int pc = 0; pc < 5; pc++) wv[pc] = w2p[pc * 512 + hg];
                    #pragma unroll
                    for (int i = 0; i < 4; i++) {
                        float2 pr = upk(acc[i][jp][q >> 1]);
                        float hv = fmaxf((q & 1) ? pr.y : pr.x, 0.f);
                        u64 hd = dup2(hv);
                        #pragma unroll
                        for (int pc = 0; pc < 5; pc++) fma2(pout[i][pc], hd, wv[pc]);
                    }
                }
        }
    }

    // ---- reduce pout across the 16 tx lanes
    #pragma unroll
    for (int i = 0; i < 4; i++)
        #pragma unroll
        for (int pc = 0; pc < 5; pc++) {
            u64 v = pout[i][pc];
            v = add2(v, __shfl_xor_sync(0xffffffffu, v, 8));
            v = add2(v, __shfl_xor_sync(0xffffffffu, v, 4));
            v = add2(v, __shfl_xor_sync(0xffffffffu, v, 2));
            v = add2(v, __shfl_xor_sync(0xffffffffu, v, 1));
            pout[i][pc] = v;
        }
    if (tx == 0) {
        #pragma unroll
        for (int i = 0; i < 4; i++)
            #pragma unroll
            for (int pc = 0; pc < 5; pc++) {
                float2 v = upk(pout[i][pc]);
                outs[(ty * 4 + i) * Ck + 2 * pc]     = v.x + __ldg(bt2 + 2 * pc);
                outs[(ty * 4 + i) * Ck + 2 * pc + 1] = v.y + __ldg(bt2 + 2 * pc + 1);
            }
    }
    __syncthreads();

    // ---- top-2 (JAX tie semantics), bitmap, per-p worklists
    if (tid < MROWS) {
        float v[Ck];
        #pragma unroll
        for (int c = 0; c < Ck; c++) v[c] = outs[tid * Ck + c];
        int i1 = 0; float m1 = v[0];
        #pragma unroll
        for (int c = 1; c < Ck; c++) if (v[c] > m1) { m1 = v[c]; i1 = c; }
        int i2 = -1; float m2 = -3.0e38f;
        #pragma unroll
        for (int c = 0; c < Ck; c++)
            if (c != i1 && v[c] > m2) { m2 = v[c]; i2 = c; }

        unsigned mask_in = 0u, mask_fb = 0u;
        #pragma unroll
        for (int p = 0; p < Pk; p++) {
            int a = __ldg(rdd + 2 * p), b = __ldg(rdd + 2 * p + 1);
            if (i1 == a && i2 == b) mask_in |= (1u << p);
            if (i1 == a)            mask_fb |= (1u << p);
        }
        unsigned m = mask_in ? mask_in : mask_fb;
        while (m) {
            int p = __ffs(m) - 1; m &= m - 1;
            int slot = atomicAdd(&cnt[p], 1);
            lists[p * MROWS + slot] = tid;
        }
    }
    __syncthreads();
    if (tid == 0) {
        int s = 0;
        #pragma unroll
        for (int p = 0; p < Pk; p++) { goff[p] = s; s += (cnt[p] + GSZ - 1) / GSZ; }
        goff[Pk] = s;
    }
    __syncthreads();

    // ---- patch phase: one warp per (p, group-of-8-rows), f32x2 + LDS.128 x
    const int ngroups = goff[Pk];
    for (int g = wid; g < ngroups; g += NWARP) {
        int p = 0;
        #pragma unroll
        for (int q = 0; q < Pk - 1; q++) if (g >= goff[q + 1]) p = q + 1;
        const int base = (g - goff[p]) * GSZ;
        const int nv   = min(GSZ, cnt[p] - base);

        int rows[GSZ];
        rows[0] = lists[p * MROWS + base];
        #pragma unroll
        for (int j = 1; j < GSZ; j++)
            rows[j] = (j < nv) ? lists[p * MROWS + base + j] : rows[0];

        const float4* wbase = (const float4*)(Wp1 + (size_t)p * Dk * HPk) + lane;
        u64 hp[GSZ][2];
        #pragma unroll
        for (int j = 0; j < GSZ; j++) { hp[j][0] = 0ull; hp[j][1] = 0ull; }

        #pragma unroll 2
        for (int d = 0; d < Dk; d += 4) {
            float4 w0 = __ldg(wbase + (d + 0) * 32);
            float4 w1 = __ldg(wbase + (d + 1) * 32);
            float4 w2 = __ldg(wbase + (d + 2) * 32);
            float4 w3 = __ldg(wbase + (d + 3) * 32);
            u64 wp0a = pk2(w0.x, w0.y), wp0b = pk2(w0.z, w0.w);
            u64 wp1a = pk2(w1.x, w1.y), wp1b = pk2(w1.z, w1.w);
            u64 wp2a = pk2(w2.x, w2.y), wp2b = pk2(w2.z, w2.w);
            u64 wp3a = pk2(w3.x, w3.y), wp3b = pk2(w3.z, w3.w);
            #pragma unroll
            for (int j = 0; j < GSZ; j++) {
                float4 xq = *(const float4*)(xs + rows[j] * XSS + d);  // broadcast LDS.128
                u64 x0 = dup2(xq.x), x1 = dup2(xq.y), x2 = dup2(xq.z), x3 = dup2(xq.w);
                fma2(hp[j][0], x0, wp0a); fma2(hp[j][1], x0, wp0b);
                fma2(hp[j][0], x1, wp1a); fma2(hp[j][1], x1, wp1b);
                fma2(hp[j][0], x2, wp2a); fma2(hp[j][1], x2, wp2b);
                fma2(hp[j][0], x3, wp3a); fma2(hp[j][1], x3, wp3b);
            }
        }

        float4 bb = __ldg((const float4*)(bp1 + p * HPk) + lane);
        u64 wq[4][5];
        #pragma unroll
        for (int q = 0; q < 4; q++) {
            const float2* wr = (const float2*)(Wp2 + ((size_t)p * HPk + lane * 4 + q) * Ck);
            #pragma unroll
            for (int pc = 0; pc < 5; pc++) {
                float2 v = __ldg(wr + pc);
                wq[q][pc] = pk2(v.x, v.y);
            }
        }

        for (int j = 0; j < nv; j++) {
            float2 h01 = upk(hp[j][0]), h23 = upk(hp[j][1]);
            u64 hd[4];
            hd[0] = dup2(fmaxf(h01.x + bb.x, 0.f));
            hd[1] = dup2(fmaxf(h01.y + bb.y, 0.f));
            hd[2] = dup2(fmaxf(h23.x + bb.z, 0.f));
            hd[3] = dup2(fmaxf(h23.y + bb.w, 0.f));
            u64 po[5];
            #pragma unroll
            for (int pc = 0; pc < 5; pc++) po[pc] = 0ull;
            #pragma unroll
            for (int q = 0; q < 4; q++)
                #pragma unroll
                for (int pc = 0; pc < 5; pc++)
                    fma2(po[pc], hd[q], wq[q][pc]);
            #pragma unroll
            for (int pc = 0; pc < 5; pc++) {
                u64 v = po[pc];
                v = add2(v, __shfl_xor_sync(0xffffffffu, v, 16));
                v = add2(v, __shfl_xor_sync(0xffffffffu, v, 8));
                v = add2(v, __shfl_xor_sync(0xffffffffu, v, 4));
                v = add2(v, __shfl_xor_sync(0xffffffffu, v, 2));
                v = add2(v, __shfl_xor_sync(0xffffffffu, v, 1));
                po[pc] = v;
            }
            if (lane == 0) {
                #pragma unroll
                for (int pc = 0; pc < 5; pc++) {
                    float2 v = upk(po[pc]);
                    atomicAdd(&outs[rows[j] * Ck + 2 * pc],
                              v.x + __ldg(bp2 + p * Ck + 2 * pc));
                    atomicAdd(&outs[rows[j] * Ck + 2 * pc + 1],
                              v.y + __ldg(bp2 + p * Ck + 2 * pc + 1));
                }
            }
        }
    }
    __syncthreads();

    // ---- final store
    for (int i = tid; i < MROWS * Ck; i += NT)
        out[(size_t)row0 * Ck + i] = outs[i];
}

extern "C" void kernel_launch(void* const* d_in, const int* in_sizes, int n_in,
                              void* d_out, int out_size)
{
    const float* x   = (const float*)d_in[0];
    const float* Wt1 = (const float*)d_in[1];
    const float* bt1 = (const float*)d_in[2];
    const float* Wt2 = (const float*)d_in[3];
    const float* bt2 = (const float*)d_in[4];
    const float* Wp1 = (const float*)d_in[5];
    const float* bp1 = (const float*)d_in[6];
    const float* Wp2 = (const float*)d_in[7];
    const float* bp2 = (const float*)d_in[8];
    const int*   rdd = (const int*)d_in[9];
    float* out = (float*)d_out;

    cudaFuncSetAttribute(netsum_kernel,
                         cudaFuncAttributeMaxDynamicSharedMemorySize, SMEM_BYTES);
    netsum_kernel<<<BT / MROWS, NT, SMEM_BYTES>>>(
        x, Wt1, bt1, Wt2, bt2, Wp1, bp1, Wp2, bp2, rdd, out);
}

// round 17
// speedup vs baseline: 2.4011x; 1.3128x over previous
#include <cuda_runtime.h>
#include <cuda_bf16.h>
#include <cstdint>

// ---------------- problem constants ----------------
#define BT   65536
#define Dk   256
#define Hk   512
#define Ck   10
#define Pk   10
#define HPk  128

#define MROWS 64
#define NT    256
#define NWARP 8
#define NSTAGE 64          // (hc 4) x (kt 16)
#define GSZ   8

// ---------------- smem layout (bytes) ----------------
#define OFF_AH    0        // A-hi frags: 64 frags x 32 x 16B = 32768 (later: patch xbufs)
#define OFF_AL    32768    // A-lo frags: 32768
#define OFF_B     65536    // B ring 2 x 8192 (later: parts u64[4][64][5] = 10240)
#define OFF_W2P   81920    // w2p u64[5][512] = 20480
#define OFF_OUTS  102400   // outs f32[64][10] = 2560
#define OFF_LIST  104960   // lists int[10][64] = 2560
#define OFF_CNT   107520   // cnt[10]
#define OFF_GOFF  107560   // goff[11]
#define OFF_FLAGC 107604
#define OFF_I12   107608   // i12[64]
#define OFF_FLAGL 107864   // flagl[64]
#define SMEM_BYTES 108160

typedef unsigned long long u64;

// ---------------- f32x2 helpers ----------------
__device__ __forceinline__ u64 pk2(float a, float b) {
    u64 r; asm("mov.b64 %0, {%1, %2};" : "=l"(r) : "f"(a), "f"(b)); return r;
}
__device__ __forceinline__ u64 dup2(float a) { return pk2(a, a); }
__device__ __forceinline__ float2 upk(u64 v) {
    float2 f; asm("mov.b64 {%0, %1}, %2;" : "=f"(f.x), "=f"(f.y) : "l"(v)); return f;
}
__device__ __forceinline__ void fma2(u64& d, u64 a, u64 b) {
    asm("fma.rn.f32x2 %0, %1, %2, %0;" : "+l"(d) : "l"(a), "l"(b));
}
__device__ __forceinline__ u64 add2(u64 a, u64 b) {
    u64 r; asm("add.rn.f32x2 %0, %1, %2;" : "=l"(r) : "l"(a), "l"(b)); return r;
}

// ---------------- cp.async ----------------
__device__ __forceinline__ uint32_t smem_u32(const void* p) {
    uint32_t a;
    asm("{ .reg .u64 t; cvta.to.shared.u64 t, %1; cvt.u32.u64 %0, t; }" : "=r"(a) : "l"(p));
    return a;
}
__device__ __forceinline__ void cp16(uint32_t dst, const void* src) {
    asm volatile("cp.async.cg.shared.global [%0], [%1], 16;" :: "r"(dst), "l"(src) : "memory");
}
#define CP_COMMIT() asm volatile("cp.async.commit_group;" ::: "memory")
#define CP_WAIT0()  asm volatile("cp.async.wait_group 0;" ::: "memory")

// ---------------- bf16 mma.sync (sm_80+ base feature) ----------------
__device__ __forceinline__ void mma_bf16(float* c, const uint32_t* a, uint32_t b0, uint32_t b1) {
    asm volatile("mma.sync.aligned.m16n8k16.row.col.f32.bf16.bf16.f32 "
                 "{%0,%1,%2,%3}, {%4,%5,%6,%7}, {%8,%9}, {%0,%1,%2,%3};"
                 : "+f"(c[0]), "+f"(c[1]), "+f"(c[2]), "+f"(c[3])
                 : "r"(a[0]), "r"(a[1]), "r"(a[2]), "r"(a[3]), "r"(b0), "r"(b1));
}

__device__ __forceinline__ void hilo(float f, uint16_t& h, uint16_t& l) {
    __nv_bfloat16 hb = __float2bfloat16_rn(f);
    float r = f - __bfloat162float(hb);
    __nv_bfloat16 lb = __float2bfloat16_rn(r);
    h = *(uint16_t*)&hb; l = *(uint16_t*)&lb;
}
__device__ __forceinline__ uint32_t pck(uint16_t lo, uint16_t hi) {
    return (uint32_t)lo | ((uint32_t)hi << 16);
}

// fragment-linear bf16 Wt1: [stage 64][entry 512] x {b0h,b1h,b0l,b1l}
__device__ __align__(16) uint4 g_Bf[NSTAGE * 512];

// ---------------- prep: Wt1 -> fragment-linear bf16 hi/lo ----------------
__global__ void prep_kernel(const float* __restrict__ Wt1) {
    const int idx = blockIdx.x * 256 + threadIdx.x;       // 0..32767
    const int s = idx >> 9, rem = idx & 511;
    const int nt = rem >> 5, t = rem & 31;
    const int hc = s >> 4, kt = s & 15;
    const int n  = hc * 128 + nt * 8 + (t >> 2);
    const int k0 = kt * 16 + (t & 3) * 2;
    float f0 = __ldg(Wt1 + (size_t)(k0 + 0) * Hk + n);
    float f1 = __ldg(Wt1 + (size_t)(k0 + 1) * Hk + n);
    float f2 = __ldg(Wt1 + (size_t)(k0 + 8) * Hk + n);
    float f3 = __ldg(Wt1 + (size_t)(k0 + 9) * Hk + n);
    uint16_t h0,l0,h1,l1,h2,l2,h3,l3;
    hilo(f0,h0,l0); hilo(f1,h1,l1); hilo(f2,h2,l2); hilo(f3,h3,l3);
    uint4 v;
    v.x = pck(h0,h1); v.y = pck(h2,h3);   // b0h, b1h
    v.z = pck(l0,l1); v.w = pck(l2,l3);   // b0l, b1l
    g_Bf[idx] = v;
}

// ---------------- main kernel ----------------
__global__ void __launch_bounds__(NT, 2)
netsum_main(const float* __restrict__ x,
            const float* __restrict__ Wt1, const float* __restrict__ bt1,
            const float* __restrict__ Wt2, const float* __restrict__ bt2,
            const float* __restrict__ Wp1, const float* __restrict__ bp1,
            const float* __restrict__ Wp2, const float* __restrict__ bp2,
            const int*   __restrict__ rdd,
            float* __restrict__ out)
{
    extern __shared__ char sm[];
    u64*   w2p   = (u64*)(sm + OFF_W2P);
    float* outs  = (float*)(sm + OFF_OUTS);
    int*   lists = (int*)(sm + OFF_LIST);
    int*   cnt   = (int*)(sm + OFF_CNT);
    int*   goff  = (int*)(sm + OFF_GOFF);
    int*   flagc = (int*)(sm + OFF_FLAGC);
    int*   i12s  = (int*)(sm + OFF_I12);
    int*   flagl = (int*)(sm + OFF_FLAGL);

    const int tid  = threadIdx.x;
    const int wid  = tid >> 5;
    const int lane = tid & 31;
    const int g    = lane >> 2, tig = lane & 3;
    const int rowg = wid & 1, colg = wid >> 1;     // 2 row-groups x 4 col-groups
    const int row0 = blockIdx.x * MROWS;

    const uint32_t bring0 = smem_u32(sm + OFF_B) + (uint32_t)tid * 32;

    // ---- issue B stage-0 prefetch
    {
        const char* src = (const char*)g_Bf + (size_t)tid * 32;
        cp16(bring0, src);
        cp16(bring0 + 16, src + 16);
    }
    CP_COMMIT();

    // ---- convert x tile -> fragment-linear A hi/lo (warp w does frags w*8..w*8+7)
    #pragma unroll
    for (int i = 0; i < 8; i++) {
        const int f = wid * 8 + i;
        const int mtg = f & 3, kt = f >> 2;
        const int r1 = mtg * 16 + g;
        const int k0 = kt * 16 + tig * 2;
        float2 p0 = __ldg((const float2*)(x + (size_t)(row0 + r1) * Dk + k0));
        float2 p1 = __ldg((const float2*)(x + (size_t)(row0 + r1) * Dk + k0 + 8));
        float2 p2 = __ldg((const float2*)(x + (size_t)(row0 + r1 + 8) * Dk + k0));
        float2 p3 = __ldg((const float2*)(x + (size_t)(row0 + r1 + 8) * Dk + k0 + 8));
        uint16_t h0a,l0a,h0b,l0b, h1a,l1a,h1b,l1b, h2a,l2a,h2b,l2b, h3a,l3a,h3b,l3b;
        hilo(p0.x,h0a,l0a); hilo(p0.y,h0b,l0b);
        hilo(p2.x,h1a,l1a); hilo(p2.y,h1b,l1b);
        hilo(p1.x,h2a,l2a); hilo(p1.y,h2b,l2b);
        hilo(p3.x,h3a,l3a); hilo(p3.y,h3b,l3b);
        uint4 ah, al;
        ah.x = pck(h0a,h0b); ah.y = pck(h1a,h1b); ah.z = pck(h2a,h2b); ah.w = pck(h3a,h3b);
        al.x = pck(l0a,l0b); al.y = pck(l1a,l1b); al.z = pck(l2a,l2b); al.w = pck(l3a,l3b);
        *(uint4*)(sm + OFF_AH + f * 512 + lane * 16) = ah;
        *(uint4*)(sm + OFF_AL + f * 512 + lane * 16) = al;
    }
    // ---- Wt2 -> packed f32x2 smem
    for (int i = tid; i < 5 * 512; i += NT) {
        const int h = i & 511, pc = i >> 9;
        float2 v = __ldg((const float2*)(Wt2 + (size_t)h * Ck) + pc);
        w2p[pc * 512 + h] = pk2(v.x, v.y);
    }
    if (tid < Pk) cnt[tid] = 0;
    if (tid == NT - 1) *flagc = 0;

    // ---- GEMM1 on tensor cores (bf16 hi/lo split), cp.async pipelined ----
    float acc[2][4][4];
    u64 pout[4][5];
    #pragma unroll
    for (int j = 0; j < 4; j++)
        #pragma unroll
        for (int pc = 0; pc < 5; pc++) pout[j][pc] = 0ull;

    #pragma unroll 1
    for (int s = 0; s < NSTAGE; s++) {
        const int hc = s >> 4, kt = s & 15;
        CP_WAIT0();
        __syncthreads();
        if (s + 1 < NSTAGE) {
            const char* src = (const char*)g_Bf + (size_t)(s + 1) * 8192 + (size_t)tid * 32;
            const uint32_t dst = bring0 + ((s + 1) & 1) * 8192;
            cp16(dst, src);
            cp16(dst + 16, src + 16);
            CP_COMMIT();
        }

        if (kt == 0) {   // init acc with bt1 (per-column bias)
            #pragma unroll
            for (int ntl = 0; ntl < 4; ntl++) {
                const int nb = hc * 128 + colg * 32 + ntl * 8 + tig * 2;
                float2 bv = __ldg((const float2*)(bt1 + nb));
                #pragma unroll
                for (int mt = 0; mt < 2; mt++) {
                    acc[mt][ntl][0] = bv.x; acc[mt][ntl][1] = bv.y;
                    acc[mt][ntl][2] = bv.x; acc[mt][ntl][3] = bv.y;
                }
            }
        }

        uint4 ah[2], al[2];
        #pragma unroll
        for (int mt = 0; mt < 2; mt++) {
            const int f = kt * 4 + rowg * 2 + mt;
            ah[mt] = *(const uint4*)(sm + OFF_AH + f * 512 + lane * 16);
            al[mt] = *(const uint4*)(sm + OFF_AL + f * 512 + lane * 16);
        }
        const char* bring = sm + OFF_B + (s & 1) * 8192;
        #pragma unroll
        for (int ntl = 0; ntl < 4; ntl++) {
            uint4 bb = *(const uint4*)(bring + ((colg * 4 + ntl) * 32 + lane) * 16);
            #pragma unroll
            for (int mt = 0; mt < 2; mt++) {
                mma_bf16(acc[mt][ntl], (const uint32_t*)&ah[mt], bb.x, bb.y);  // Ah*Bh
                mma_bf16(acc[mt][ntl], (const uint32_t*)&ah[mt], bb.z, bb.w);  // Ah*Bl
                mma_bf16(acc[mt][ntl], (const uint32_t*)&al[mt], bb.x, bb.y);  // Al*Bh
            }
        }

        if (kt == 15) {   // GEMM2 partials for this hc
            #pragma unroll
            for (int ntl = 0; ntl < 4; ntl++) {
                const int nb = hc * 128 + colg * 32 + ntl * 8 + tig * 2;
                u64 w0[5], w1[5];
                #pragma unroll
                for (int pc = 0; pc < 5; pc++) {
                    w0[pc] = w2p[pc * 512 + nb];
                    w1[pc] = w2p[pc * 512 + nb + 1];
                }
                #pragma unroll
                for (int mt = 0; mt < 2; mt++) {
                    u64 hc0 = dup2(fmaxf(acc[mt][ntl][0], 0.f));
                    u64 hc1 = dup2(fmaxf(acc[mt][ntl][1], 0.f));
                    u64 hc2 = dup2(fmaxf(acc[mt][ntl][2], 0.f));
                    u64 hc3 = dup2(fmaxf(acc[mt][ntl][3], 0.f));
                    #pragma unroll
                    for (int pc = 0; pc < 5; pc++) {
                        fma2(pout[mt * 2 + 0][pc], hc0, w0[pc]);
                        fma2(pout[mt * 2 + 0][pc], hc1, w1[pc]);
                        fma2(pout[mt * 2 + 1][pc], hc2, w0[pc]);
                        fma2(pout[mt * 2 + 1][pc], hc3, w1[pc]);
                    }
                }
            }
        }
    }
    __syncthreads();   // B ring dead -> safe to overlay parts

    // ---- reduce pout over tig lanes; store parts[colg][row][5]
    u64* parts = (u64*)(sm + OFF_B);
    #pragma unroll
    for (int j = 0; j < 4; j++)
        #pragma unroll
        for (int pc = 0; pc < 5; pc++) {
            u64 v = pout[j][pc];
            v = add2(v, __shfl_xor_sync(0xffffffffu, v, 1));
            v = add2(v, __shfl_xor_sync(0xffffffffu, v, 2));
            pout[j][pc] = v;
        }
    if (tig == 0) {
        #pragma unroll
        for (int j = 0; j < 4; j++) {
            const int row = rowg * 32 + (j >> 1) * 16 + g + (j & 1) * 8;
            #pragma unroll
            for (int pc = 0; pc < 5; pc++)
                parts[(colg * 64 + row) * 5 + pc] = pout[j][pc];
        }
    }
    __syncthreads();

    // ---- combine + top2 + margin flags ----
    if (tid < MROWS) {
        float v[Ck];
        #pragma unroll
        for (int pc = 0; pc < 5; pc++) {
            u64 t = parts[(0 * 64 + tid) * 5 + pc];
            t = add2(t, parts[(1 * 64 + tid) * 5 + pc]);
            t = add2(t, parts[(2 * 64 + tid) * 5 + pc]);
            t = add2(t, parts[(3 * 64 + tid) * 5 + pc]);
            float2 f = upk(t);
            v[2 * pc]     = f.x + __ldg(bt2 + 2 * pc);
            v[2 * pc + 1] = f.y + __ldg(bt2 + 2 * pc + 1);
        }
        #pragma unroll
        for (int c = 0; c < Ck; c++) outs[tid * Ck + c] = v[c];
        int i1 = 0; float m1 = v[0];
        #pragma unroll
        for (int c = 1; c < Ck; c++) if (v[c] > m1) { m1 = v[c]; i1 = c; }
        int i2 = -1; float m2 = -3.0e38f;
        #pragma unroll
        for (int c = 0; c < Ck; c++) if (c != i1 && v[c] > m2) { m2 = v[c]; i2 = c; }
        float m3 = -3.0e38f;
        #pragma unroll
        for (int c = 0; c < Ck; c++) if (c != i1 && c != i2 && v[c] > m3) m3 = v[c];
        i12s[tid] = i1 * 16 + i2;
        if (m1 - m2 < 1e-3f || m2 - m3 < 1e-3f) {
            int sIdx = atomicAdd(flagc, 1);
            flagl[sIdx] = tid;
        }
    }
    __syncthreads();

    // ---- exact fp32 recompute for margin-ambiguous rows (rare) ----
    const int nflag = *flagc;
    for (int fi = wid; fi < nflag; fi += NWARP) {
        const int r = flagl[fi];
        const float* xr = x + (size_t)(row0 + r) * Dk;
        float po[Ck];
        #pragma unroll
        for (int c = 0; c < Ck; c++) po[c] = 0.f;
        for (int hh = lane; hh < Hk; hh += 32) {
            float a = __ldg(bt1 + hh);
            for (int d = 0; d < Dk; d++)
                a += __ldg(xr + d) * __ldg(Wt1 + (size_t)d * Hk + hh);
            a = fmaxf(a, 0.f);
            #pragma unroll
            for (int pc = 0; pc < 5; pc++) {
                float2 w = upk(w2p[pc * 512 + hh]);
                po[2 * pc] += a * w.x; po[2 * pc + 1] += a * w.y;
            }
        }
        #pragma unroll
        for (int c = 0; c < Ck; c++) {
            float sv = po[c];
            sv += __shfl_xor_sync(0xffffffffu, sv, 16);
            sv += __shfl_xor_sync(0xffffffffu, sv, 8);
            sv += __shfl_xor_sync(0xffffffffu, sv, 4);
            sv += __shfl_xor_sync(0xffffffffu, sv, 2);
            sv += __shfl_xor_sync(0xffffffffu, sv, 1);
            po[c] = sv;
        }
        if (lane == 0) {
            float v[Ck];
            #pragma unroll
            for (int c = 0; c < Ck; c++) { v[c] = po[c] + __ldg(bt2 + c); outs[r * Ck + c] = v[c]; }
            int i1 = 0; float m1 = v[0];
            #pragma unroll
            for (int c = 1; c < Ck; c++) if (v[c] > m1) { m1 = v[c]; i1 = c; }
            int i2 = -1; float m2 = -3.0e38f;
            #pragma unroll
            for (int c = 0; c < Ck; c++) if (c != i1 && v[c] > m2) { m2 = v[c]; i2 = c; }
            i12s[r] = i1 * 16 + i2;
        }
    }
    __syncthreads();

    // ---- bitmap + per-p worklists ----
    if (tid < MROWS) {
        const int vv = i12s[tid], i1 = vv >> 4, i2 = vv & 15;
        unsigned mask_in = 0u, mask_fb = 0u;
        #pragma unroll
        for (int p = 0; p < Pk; p++) {
            int a = __ldg(rdd + 2 * p), b = __ldg(rdd + 2 * p + 1);
            if (i1 == a && i2 == b) mask_in |= (1u << p);
            if (i1 == a)            mask_fb |= (1u << p);
        }
        unsigned m = mask_in ? mask_in : mask_fb;
        while (m) {
            int p = __ffs(m) - 1; m &= m - 1;
            int slot = atomicAdd(&cnt[p], 1);
            lists[p * MROWS + slot] = tid;
        }
    }
    __syncthreads();
    if (tid == 0) {
        int s = 0;
        #pragma unroll
        for (int p = 0; p < Pk; p++) { goff[p] = s; s += (cnt[p] + GSZ - 1) / GSZ; }
        goff[Pk] = s;
    }
    __syncthreads();

    // ---- patch phase: one warp per (p, group-of-8-rows); x in per-warp smem buf
    const int ngroups = goff[Pk];
    float* xbuf = (float*)(sm + OFF_AH) + wid * 2048;   // 8KB per warp (A frags dead)
    for (int gi = wid; gi < ngroups; gi += NWARP) {
        int p = 0;
        #pragma unroll
        for (int q = 0; q < Pk - 1; q++) if (gi >= goff[q + 1]) p = q + 1;
        const int base = (gi - goff[p]) * GSZ;
        const int nv   = min(GSZ, cnt[p] - base);

        int rows[GSZ];
        rows[0] = lists[p * MROWS + base];
        #pragma unroll
        for (int j = 1; j < GSZ; j++)
            rows[j] = (j < nv) ? lists[p * MROWS + base + j] : rows[0];

        __syncwarp();
        for (int t = lane; t < 512; t += 32) {
            const int j = t >> 6, e = t & 63;
            ((float4*)xbuf)[t] = __ldg((const float4*)x + (size_t)(row0 + rows[j]) * 64 + e);
        }
        __syncwarp();

        const float4* wbase = (const float4*)(Wp1 + (size_t)p * Dk * HPk) + lane;
        u64 hp[GSZ][2];
        #pragma unroll
        for (int j = 0; j < GSZ; j++) { hp[j][0] = 0ull; hp[j][1] = 0ull; }

        #pragma unroll 2
        for (int d = 0; d < Dk; d += 4) {
            float4 w0 = __ldg(wbase + (d + 0) * 32);
            float4 w1 = __ldg(wbase + (d + 1) * 32);
            float4 w2 = __ldg(wbase + (d + 2) * 32);
            float4 w3 = __ldg(wbase + (d + 3) * 32);
            u64 wp0a = pk2(w0.x, w0.y), wp0b = pk2(w0.z, w0.w);
            u64 wp1a = pk2(w1.x, w1.y), wp1b = pk2(w1.z, w1.w);
            u64 wp2a = pk2(w2.x, w2.y), wp2b = pk2(w2.z, w2.w);
            u64 wp3a = pk2(w3.x, w3.y), wp3b = pk2(w3.z, w3.w);
            #pragma unroll
            for (int j = 0; j < GSZ; j++) {
                float4 xq = *(const float4*)(xbuf + j * 256 + d);
                u64 x0 = dup2(xq.x), x1 = dup2(xq.y), x2 = dup2(xq.z), x3 = dup2(xq.w);
                fma2(hp[j][0], x0, wp0a); fma2(hp[j][1], x0, wp0b);
                fma2(hp[j][0], x1, wp1a); fma2(hp[j][1], x1, wp1b);
                fma2(hp[j][0], x2, wp2a); fma2(hp[j][1], x2, wp2b);
                fma2(hp[j][0], x3, wp3a); fma2(hp[j][1], x3, wp3b);
            }
        }

        float4 bb = __ldg((const float4*)(bp1 + p * HPk) + lane);
        u64 wq[4][5];
        #pragma unroll
        for (int q = 0; q < 4; q++) {
            const float2* wr = (const float2*)(Wp2 + ((size_t)p * HPk + lane * 4 + q) * Ck);
            #pragma unroll
            for (int pc = 0; pc < 5; pc++) {
                float2 v = __ldg(wr + pc);
                wq[q][pc] = pk2(v.x, v.y);
            }
        }

        for (int j = 0; j < nv; j++) {
            float2 h01 = upk(hp[j][0]), h23 = upk(hp[j][1]);
            u64 hd[4];
            hd[0] = dup2(fmaxf(h01.x + bb.x, 0.f));
            hd[1] = dup2(fmaxf(h01.y + bb.y, 0.f));
            hd[2] = dup2(fmaxf(h23.x + bb.z, 0.f));
            hd[3] = dup2(fmaxf(h23.y + bb.w, 0.f));
            u64 po[5];
            #pragma unroll
            for (int pc = 0; pc < 5; pc++) po[pc] = 0ull;
            #pragma unroll
            for (int q = 0; q < 4; q++)
                #pragma unroll
                for (int pc = 0; pc < 5; pc++)
                    fma2(po[pc], hd[q], wq[q][pc]);
            #pragma unroll
            for (int pc = 0; pc < 5; pc++) {
                u64 v = po[pc];
                v = add2(v, __shfl_xor_sync(0xffffffffu, v, 16));
                v = add2(v, __shfl_xor_sync(0xffffffffu, v, 8));
                v = add2(v, __shfl_xor_sync(0xffffffffu, v, 4));
                v = add2(v, __shfl_xor_sync(0xffffffffu, v, 2));
                v = add2(v, __shfl_xor_sync(0xffffffffu, v, 1));
                po[pc] = v;
            }
            if (lane == 0) {
                #pragma unroll
                for (int pc = 0; pc < 5; pc++) {
                    float2 v = upk(po[pc]);
                    atomicAdd(&outs[rows[j] * Ck + 2 * pc],
                              v.x + __ldg(bp2 + p * Ck + 2 * pc));
                    atomicAdd(&outs[rows[j] * Ck + 2 * pc + 1],
                              v.y + __ldg(bp2 + p * Ck + 2 * pc + 1));
                }
            }
        }
    }
    __syncthreads();

    // ---- final store
    for (int i = tid; i < MROWS * Ck; i += NT)
        out[(size_t)row0 * Ck + i] = outs[i];
}

extern "C" void kernel_launch(void* const* d_in, const int* in_sizes, int n_in,
                              void* d_out, int out_size)
{
    const float* x   = (const float*)d_in[0];
    const float* Wt1 = (const float*)d_in[1];
    const float* bt1 = (const float*)d_in[2];
    const float* Wt2 = (const float*)d_in[3];
    const float* bt2 = (const float*)d_in[4];
    const float* Wp1 = (const float*)d_in[5];
    const float* bp1 = (const float*)d_in[6];
    const float* Wp2 = (const float*)d_in[7];
    const float* bp2 = (const float*)d_in[8];
    const int*   rdd = (const int*)d_in[9];
    float* out = (float*)d_out;

    prep_kernel<<<128, 256>>>(Wt1);

    cudaFuncSetAttribute(netsum_main,
                         cudaFuncAttributeMaxDynamicSharedMemorySize, SMEM_BYTES);
    netsum_main<<<BT / MROWS, NT, SMEM_BYTES>>>(
        x, Wt1, bt1, Wt2, bt2, Wp1, bp1, Wp2, bp2, rdd, out);
}